// round 6
// baseline (speedup 1.0000x reference)
#include <cuda_runtime.h>
#include <cuda_bf16.h>
#include <math.h>

// Problem constants
#define MB   64
#define C    24
#define D    8
#define S2   64          // D*D
#define QS   128
#define H    256
#define OUT  28

// GEMM tiling
#define TM   128         // pair-rows per CTA
#define KT   32          // K-chunk staged in smem
#define HSTR 260         // padded row stride for activation smem (float4-aligned)

// Scratch (static device globals; no allocation allowed)
__device__ float g_u[MB * S2 * H];   // 4 MB
__device__ float g_v[MB * S2 * H];   // 4 MB
__device__ float g_xg[MB * H];       // per-batch pair sums

// ---------- packed f32x2 helpers (FFMA2: 2x fp32 throughput on sm_103a) ----------
__device__ __forceinline__ unsigned long long pack2(float lo, float hi) {
    unsigned long long r;
    asm("mov.b64 %0, {%1, %2};" : "=l"(r) : "f"(lo), "f"(hi));
    return r;
}
__device__ __forceinline__ void unpack2(unsigned long long v, float& lo, float& hi) {
    asm("mov.b64 {%0, %1}, %2;" : "=f"(lo), "=f"(hi) : "l"(v));
}
__device__ __forceinline__ unsigned long long fma2(unsigned long long a,
                                                   unsigned long long b,
                                                   unsigned long long c) {
    unsigned long long d;
    asm("fma.rn.f32x2 %0, %1, %2, %3;" : "=l"(d) : "l"(a), "l"(b), "l"(c));
    return d;
}

// =====================================================================
// Kernel 1: u[b,q,n] = x_flat[b,q] . Wi[n],  v[b,p,n] = x_flat[b,p] . Wj[n] + qst[b].Wq[n] + bg1[n]
// Also zeroes g_xg.
// =====================================================================
__global__ void k_uv(const float* __restrict__ x, const float* __restrict__ qst,
                     const float* __restrict__ Wg1, const float* __restrict__ bg1) {
    int b = blockIdx.x;
    int tid = threadIdx.x;   // 256 threads, tid == output index n

    __shared__ float xf[S2][C + 2];   // 64 x 26
    __shared__ float qs[QS];

    // load x channels (coalesced over s)
    for (int i = tid; i < S2 * C; i += 256) {
        int c = i / S2, s = i % S2;
        xf[s][c] = x[(b * C + c) * S2 + s];
    }
    if (tid < QS) qs[tid] = qst[b * QS + tid];
    if (tid < S2) {
        int s = tid;
        xf[s][24] = ((s >> 3) - 4) * 0.25f;   // cx = (a//d - d/2)/(d/2)
        xf[s][25] = ((s & 7) - 4) * 0.25f;    // cy
    }
    g_xg[b * H + tid] = 0.0f;
    __syncthreads();

    const int n = tid;
    const float* wr = Wg1 + n * 180;
    float Wi[26], Wj[26];
#pragma unroll
    for (int c = 0; c < 26; c++) { Wi[c] = wr[c]; Wj[c] = wr[26 + c]; }

    float qw = bg1[n];
#pragma unroll 8
    for (int j = 0; j < QS; j++) qw += qs[j] * wr[52 + j];

    for (int s = 0; s < S2; s++) {
        float su = 0.0f, sv = 0.0f;
#pragma unroll
        for (int c = 0; c < 26; c++) {
            float xv = xf[s][c];
            su += xv * Wi[c];
            sv += xv * Wj[c];
        }
        g_u[(b * S2 + s) * H + n] = su;
        g_v[(b * S2 + s) * H + n] = sv + qw;
    }
}

// =====================================================================
// Kernel 2: main g-MLP over all pairs. One CTA = 128 pairs x 256 cols.
//   h1 = relu(u[q] + v[p]) built in smem; 3 GEMMs (K streamed in 32-chunks),
//   ReLU in-place; layer-4 outputs summed over rows -> atomicAdd into g_xg.
// =====================================================================
__global__ void __launch_bounds__(256, 1)
k_g(const float* __restrict__ Wg2, const float* __restrict__ bg2,
    const float* __restrict__ Wg3, const float* __restrict__ bg3,
    const float* __restrict__ Wg4, const float* __restrict__ bg4) {
    extern __shared__ float sm[];
    float* hA = sm;                 // [128][HSTR]
    float* ws = sm + TM * HSTR;     // [KT][HSTR]  (also reused as reduction buffer)

    const int b    = blockIdx.y;
    const int tile = blockIdx.x;    // 0..31 : 128 consecutive pair indices
    const int tid  = threadIdx.x;
    const int tx   = tid & 15;      // 16 col-groups of 16
    const int ty   = tid >> 4;      // 16 row-groups of 8
    const int rb   = ty * 8;
    const int cb   = tx * 16;

    const float* ub = g_u + b * S2 * H;
    const float* vb = g_v + b * S2 * H;

    // ---- build h1 = relu(u[q] + v[p]) ----
#pragma unroll
    for (int rr = 0; rr < 8; rr++) {
        int r = rb + rr;
        int q = r & 63;
        int p = tile * 2 + (r >> 6);
        const float4* u4 = (const float4*)(ub + q * H + cb);
        const float4* v4 = (const float4*)(vb + p * H + cb);
        float4* h4 = (float4*)(hA + r * HSTR + cb);
#pragma unroll
        for (int j = 0; j < 4; j++) {
            float4 uu = u4[j], vv = v4[j], hh;
            hh.x = fmaxf(uu.x + vv.x, 0.0f);
            hh.y = fmaxf(uu.y + vv.y, 0.0f);
            hh.z = fmaxf(uu.z + vv.z, 0.0f);
            hh.w = fmaxf(uu.w + vv.w, 0.0f);
            h4[j] = hh;
        }
    }

    const float* Wl[3] = {Wg2, Wg3, Wg4};
    const float* bl[3] = {bg2, bg3, bg4};

    float csum[16];
#pragma unroll
    for (int cc = 0; cc < 16; cc++) csum[cc] = 0.0f;

    unsigned long long acc[8][8];   // 8 rows x 8 col-pairs (f32x2)

    for (int L = 0; L < 3; L++) {
        const float* W = Wl[L];
#pragma unroll
        for (int rr = 0; rr < 8; rr++)
#pragma unroll
            for (int jp = 0; jp < 8; jp++) acc[rr][jp] = 0ULL;

        for (int kt = 0; kt < H; kt += KT) {
            __syncthreads();   // prior chunk compute done / hA writes visible
            // stage+transpose weight chunk: ws[k][n] = W[n*256 + kt + k]
            {
                const float4* src = (const float4*)(W + tid * H + kt);
#pragma unroll
                for (int j4 = 0; j4 < KT / 4; j4++) {
                    float4 wv = src[j4];
                    ws[(j4 * 4 + 0) * HSTR + tid] = wv.x;
                    ws[(j4 * 4 + 1) * HSTR + tid] = wv.y;
                    ws[(j4 * 4 + 2) * HSTR + tid] = wv.z;
                    ws[(j4 * 4 + 3) * HSTR + tid] = wv.w;
                }
            }
            __syncthreads();

            const float* abase = hA + kt;
#pragma unroll 2
            for (int k = 0; k < KT; k++) {
                unsigned long long aa[8];
#pragma unroll
                for (int rr = 0; rr < 8; rr++) {
                    float a = abase[(rb + rr) * HSTR + k];
                    aa[rr] = pack2(a, a);
                }
                const float4* wrow = (const float4*)(ws + k * HSTR + cb);
#pragma unroll
                for (int j = 0; j < 4; j++) {
                    float4 wv = wrow[j];
                    unsigned long long b01 = pack2(wv.x, wv.y);
                    unsigned long long b23 = pack2(wv.z, wv.w);
#pragma unroll
                    for (int rr = 0; rr < 8; rr++) {
                        acc[rr][2 * j]     = fma2(aa[rr], b01, acc[rr][2 * j]);
                        acc[rr][2 * j + 1] = fma2(aa[rr], b23, acc[rr][2 * j + 1]);
                    }
                }
            }
        }
        __syncthreads();   // all reads of hA for this layer complete

        const float* bias = bl[L];
        float bb[16];
#pragma unroll
        for (int cc = 0; cc < 16; cc++) bb[cc] = bias[cb + cc];

        if (L < 2) {
            // ReLU(acc + bias) -> back into hA
#pragma unroll
            for (int rr = 0; rr < 8; rr++) {
                float* hw = hA + (rb + rr) * HSTR + cb;
#pragma unroll
                for (int jp = 0; jp < 8; jp++) {
                    float f0, f1;
                    unpack2(acc[rr][jp], f0, f1);
                    hw[2 * jp]     = fmaxf(f0 + bb[2 * jp], 0.0f);
                    hw[2 * jp + 1] = fmaxf(f1 + bb[2 * jp + 1], 0.0f);
                }
            }
        } else {
            // layer 4: accumulate per-column sums over this thread's 8 rows
#pragma unroll
            for (int rr = 0; rr < 8; rr++) {
#pragma unroll
                for (int jp = 0; jp < 8; jp++) {
                    float f0, f1;
                    unpack2(acc[rr][jp], f0, f1);
                    csum[2 * jp]     += fmaxf(f0 + bb[2 * jp], 0.0f);
                    csum[2 * jp + 1] += fmaxf(f1 + bb[2 * jp + 1], 0.0f);
                }
            }
        }
    }

    // cross-ty reduction of csum via ws buffer (16 x 256 floats fits)
    float* red = ws;
#pragma unroll
    for (int cc = 0; cc < 16; cc++) red[ty * H + cb + cc] = csum[cc];
    __syncthreads();

    float tot = 0.0f;
#pragma unroll
    for (int t = 0; t < 16; t++) tot += red[t * H + tid];
    atomicAdd(&g_xg[b * H + tid], tot);
}

// =====================================================================
// Kernel 3: f-MLP (256->256->256->28) + log_softmax, one block per batch row.
// =====================================================================
__global__ void k_f(const float* __restrict__ Wf1, const float* __restrict__ bf1,
                    const float* __restrict__ Wf2, const float* __restrict__ bf2,
                    const float* __restrict__ Wf3, const float* __restrict__ bf3,
                    float* __restrict__ out) {
    int b = blockIdx.x;
    int tid = threadIdx.x, lane = tid & 31, w = tid >> 5;  // 8 warps

    __shared__ float xs[H], f1s[H], f2s[H], ls[32];

    xs[tid] = g_xg[b * H + tid];
    __syncthreads();

    // f1
    for (int i = 0; i < 32; i++) {
        int n = w * 32 + i;
        float p = 0.0f;
#pragma unroll
        for (int j = 0; j < 8; j++) {
            int k = lane + 32 * j;
            p += xs[k] * Wf1[n * H + k];
        }
#pragma unroll
        for (int off = 16; off > 0; off >>= 1) p += __shfl_xor_sync(0xffffffffu, p, off);
        if (lane == 0) f1s[n] = fmaxf(p + bf1[n], 0.0f);
    }
    __syncthreads();

    // f2
    for (int i = 0; i < 32; i++) {
        int n = w * 32 + i;
        float p = 0.0f;
#pragma unroll
        for (int j = 0; j < 8; j++) {
            int k = lane + 32 * j;
            p += f1s[k] * Wf2[n * H + k];
        }
#pragma unroll
        for (int off = 16; off > 0; off >>= 1) p += __shfl_xor_sync(0xffffffffu, p, off);
        if (lane == 0) f2s[n] = fmaxf(p + bf2[n], 0.0f);
    }
    __syncthreads();

    // logits (28 outputs)
    for (int i = 0; i < 4; i++) {
        int n = w * 4 + i;
        if (n < OUT) {
            float p = 0.0f;
#pragma unroll
            for (int j = 0; j < 8; j++) {
                int k = lane + 32 * j;
                p += f2s[k] * Wf3[n * H + k];
            }
#pragma unroll
            for (int off = 16; off > 0; off >>= 1) p += __shfl_xor_sync(0xffffffffu, p, off);
            if (lane == 0) ls[n] = p + bf3[n];
        }
    }
    __syncthreads();

    if (w == 0) {
        float v = (lane < OUT) ? ls[lane] : -3.4e38f;
        float m = v;
#pragma unroll
        for (int off = 16; off > 0; off >>= 1) m = fmaxf(m, __shfl_xor_sync(0xffffffffu, m, off));
        float e = (lane < OUT) ? expf(v - m) : 0.0f;
        float s = e;
#pragma unroll
        for (int off = 16; off > 0; off >>= 1) s += __shfl_xor_sync(0xffffffffu, s, off);
        float lse = logf(s) + m;
        if (lane < OUT) out[b * OUT + lane] = v - lse;
    }
}

// =====================================================================
extern "C" void kernel_launch(void* const* d_in, const int* in_sizes, int n_in,
                              void* d_out, int out_size) {
    (void)in_sizes; (void)n_in; (void)out_size;
    const float* x   = (const float*)d_in[0];
    const float* qst = (const float*)d_in[1];
    const float* Wg1 = (const float*)d_in[2];
    const float* bg1 = (const float*)d_in[3];
    const float* Wg2 = (const float*)d_in[4];
    const float* bg2 = (const float*)d_in[5];
    const float* Wg3 = (const float*)d_in[6];
    const float* bg3 = (const float*)d_in[7];
    const float* Wg4 = (const float*)d_in[8];
    const float* bg4 = (const float*)d_in[9];
    const float* Wf1 = (const float*)d_in[10];
    const float* bf1 = (const float*)d_in[11];
    const float* Wf2 = (const float*)d_in[12];
    const float* bf2 = (const float*)d_in[13];
    const float* Wf3 = (const float*)d_in[14];
    const float* bf3 = (const float*)d_in[15];

    const size_t smem = (size_t)(TM * HSTR + KT * HSTR) * sizeof(float);  // ~162.5 KB
    cudaFuncSetAttribute(k_g, cudaFuncAttributeMaxDynamicSharedMemorySize, (int)smem);

    k_uv<<<MB, 256>>>(x, qst, Wg1, bg1);
    k_g<<<dim3(S2 * S2 / TM, MB), 256, smem>>>(Wg2, bg2, Wg3, bg3, Wg4, bg4);
    k_f<<<MB, 256>>>(Wf1, bf1, Wf2, bf2, Wf3, bf3, (float*)d_out);
}

// round 8
// speedup vs baseline: 6.4789x; 6.4789x over previous
#include <cuda_runtime.h>
#include <cuda_bf16.h>
#include <cstdint>
#include <math.h>

#define MB   64
#define C    24
#define S2   64
#define QS   128
#define H    256
#define OUT  28

#define PADA 260            // hA row stride (floats)
#define PADW 36             // ws row stride (floats)
#define NTHREADS 512

// ---------------- scratch (static device globals) ----------------
__device__ float g_u[MB * S2 * H];
__device__ float g_v[MB * S2 * H];
__device__ float g_xg[MB * H];

// ---------------- helpers ----------------
__device__ __forceinline__ uint32_t smem_u32(const void* p) {
    uint32_t a;
    asm("{ .reg .u64 t; cvta.to.shared.u64 t, %1; cvt.u32.u64 %0, t; }" : "=r"(a) : "l"(p));
    return a;
}
__device__ __forceinline__ float tf32r(float x) {   // round-to-nearest tf32
    uint32_t u;
    asm("cvt.rna.tf32.f32 %0, %1;" : "=r"(u) : "f"(x));
    return __uint_as_float(u);
}
__device__ __forceinline__ uint32_t tf32u(float x) {
    uint32_t u;
    asm("cvt.rna.tf32.f32 %0, %1;" : "=r"(u) : "f"(x));
    return u;
}
__device__ __forceinline__ void cp16(uint32_t dst, const void* src) {
    asm volatile("cp.async.ca.shared.global [%0], [%1], 16;" :: "r"(dst), "l"(src) : "memory");
}
__device__ __forceinline__ void cp_commit() {
    asm volatile("cp.async.commit_group;" ::: "memory");
}
__device__ __forceinline__ void mma_tf32(float* d, const uint32_t* a, const uint32_t* b) {
    asm volatile(
        "mma.sync.aligned.m16n8k8.row.col.f32.tf32.tf32.f32 "
        "{%0,%1,%2,%3}, {%4,%5,%6,%7}, {%8,%9}, {%0,%1,%2,%3};"
        : "+f"(d[0]), "+f"(d[1]), "+f"(d[2]), "+f"(d[3])
        : "r"(a[0]), "r"(a[1]), "r"(a[2]), "r"(a[3]), "r"(b[0]), "r"(b[1]));
}

// =====================================================================
// Kernel 1: u/v precompute (grid (MB,4): each block covers 16 s rows)
// =====================================================================
__global__ void k_uv(const float* __restrict__ x, const float* __restrict__ qst,
                     const float* __restrict__ Wg1, const float* __restrict__ bg1) {
    int b = blockIdx.x, seg = blockIdx.y;
    int tid = threadIdx.x;

    __shared__ float xf[16][26];
    __shared__ float qs[QS];

    for (int i = tid; i < 16 * C; i += 256) {
        int c = i / 16, sl = i % 16;
        xf[sl][c] = x[(b * C + c) * S2 + seg * 16 + sl];
    }
    if (tid < QS) qs[tid] = qst[b * QS + tid];
    if (tid < 16) {
        int s = seg * 16 + tid;
        xf[tid][24] = ((s >> 3) - 4) * 0.25f;
        xf[tid][25] = ((s & 7) - 4) * 0.25f;
    }
    if (seg == 0) g_xg[b * H + tid] = 0.0f;
    __syncthreads();

    const int n = tid;
    const float* wr = Wg1 + n * 180;
    float Wi[26], Wj[26];
#pragma unroll
    for (int c = 0; c < 26; c++) { Wi[c] = wr[c]; Wj[c] = wr[26 + c]; }

    float qw = bg1[n];
#pragma unroll 8
    for (int j = 0; j < QS; j++) qw += qs[j] * wr[52 + j];

    for (int sl = 0; sl < 16; sl++) {
        float su = 0.0f, sv = 0.0f;
#pragma unroll
        for (int c = 0; c < 26; c++) {
            float xv = xf[sl][c];
            su += xv * Wi[c];
            sv += xv * Wj[c];
        }
        int s = seg * 16 + sl;
        g_u[(b * S2 + s) * H + n] = su;
        g_v[(b * S2 + s) * H + n] = sv + qw;
    }
}

// =====================================================================
// Kernel 2: tf32 mma.sync g-MLP. CTA = (batch, 2 p-rows) -> M=128 pairs.
//   512 threads = 16 warps in 4(m) x 4(n); warp tile 32x64.
// =====================================================================
__global__ void __launch_bounds__(NTHREADS, 1)
k_g(const float* __restrict__ Wg2, const float* __restrict__ bg2,
    const float* __restrict__ Wg3, const float* __restrict__ bg3,
    const float* __restrict__ Wg4, const float* __restrict__ bg4) {
    extern __shared__ float sm[];
    float* sbias = sm;                         // 256 f
    float* hA    = sm + 256;                   // 128 x PADA
    float* ws[2];
    ws[0] = hA + 128 * PADA;                   // 256 x PADW
    ws[1] = ws[0] + 256 * PADW;

    const int b = blockIdx.y, tile = blockIdx.x;
    const int tid = threadIdx.x, wid = tid >> 5, lane = tid & 31;
    const int mbase = (wid & 3) * 32;          // warp m-offset
    const int nbase = (wid >> 2) * 64;         // warp n-offset
    const int lr = lane >> 2;                  // 0..7  (row within 8-group)
    const int lc = lane & 3;                   // 0..3  (k/col sub-index)

    // ---- build h1 = relu(u[q] + v[p]) ----
    const float* ub = g_u + b * S2 * H;
    const float* vb = g_v + b * S2 * H;
    for (int i = tid; i < 128 * 64; i += NTHREADS) {
        int r = i >> 6;
        int k4 = (i & 63) << 2;
        int q = r & 63, p = tile * 2 + (r >> 6);
        float4 uu = *(const float4*)(ub + q * H + k4);
        float4 vv = *(const float4*)(vb + p * H + k4);
        float4 hh;
        hh.x = tf32r(fmaxf(uu.x + vv.x, 0.0f));
        hh.y = tf32r(fmaxf(uu.y + vv.y, 0.0f));
        hh.z = tf32r(fmaxf(uu.z + vv.z, 0.0f));
        hh.w = tf32r(fmaxf(uu.w + vv.w, 0.0f));
        *(float4*)(hA + r * PADA + k4) = hh;
    }

    const float* Wl[3] = {Wg2, Wg3, Wg4};
    const float* bl[3] = {bg2, bg3, bg4};

    for (int L = 0; L < 3; L++) {
        const float* W = Wl[L];
        if (tid < 256) sbias[tid] = bl[L][tid];

        float acc[2][8][4];
#pragma unroll
        for (int mt = 0; mt < 2; mt++)
#pragma unroll
            for (int nt = 0; nt < 8; nt++)
#pragma unroll
                for (int i = 0; i < 4; i++) acc[mt][nt][i] = 0.0f;

        // prologue: stage chunk 0
        {
            const uint32_t dbase = smem_u32(ws[0]);
#pragma unroll
            for (int it = 0; it < 4; it++) {
                int idx = tid + it * NTHREADS;       // 0..2047
                int n = idx >> 3, q = idx & 7;
                cp16(dbase + (uint32_t)(n * PADW + q * 4) * 4, W + n * H + q * 4);
            }
            cp_commit();
        }

        for (int c = 0; c < 8; c++) {
            if (c < 7) {   // stage chunk c+1 into other buffer
                const uint32_t dbase = smem_u32(ws[(c + 1) & 1]);
                const float* Wc = W + (c + 1) * 32;
#pragma unroll
                for (int it = 0; it < 4; it++) {
                    int idx = tid + it * NTHREADS;
                    int n = idx >> 3, q = idx & 7;
                    cp16(dbase + (uint32_t)(n * PADW + q * 4) * 4, Wc + n * H + q * 4);
                }
                cp_commit();
                asm volatile("cp.async.wait_group 1;" ::: "memory");
            } else {
                asm volatile("cp.async.wait_group 0;" ::: "memory");
            }
            __syncthreads();

            const float* wb = ws[c & 1];
#pragma unroll
            for (int k8 = 0; k8 < 4; k8++) {
                const int kg = c * 32 + k8 * 8 + lc;   // A col
                const int kw = k8 * 8 + lc;            // ws col
                uint32_t afr[2][4];
#pragma unroll
                for (int mt = 0; mt < 2; mt++) {
                    const float* ar = hA + (mbase + mt * 16 + lr) * PADA + kg;
                    afr[mt][0] = __float_as_uint(ar[0]);
                    afr[mt][1] = __float_as_uint(ar[8 * PADA]);
                    afr[mt][2] = __float_as_uint(ar[4]);
                    afr[mt][3] = __float_as_uint(ar[8 * PADA + 4]);
                }
                uint32_t bfr[8][2];
#pragma unroll
                for (int nt = 0; nt < 8; nt++) {
                    const float* br = wb + (nbase + nt * 8 + lr) * PADW + kw;
                    bfr[nt][0] = tf32u(br[0]);
                    bfr[nt][1] = tf32u(br[4]);
                }
#pragma unroll
                for (int mt = 0; mt < 2; mt++)
#pragma unroll
                    for (int nt = 0; nt < 8; nt++)
                        mma_tf32(acc[mt][nt], afr[mt], bfr[nt]);
            }
            __syncthreads();   // reads of ws[c&1] done before it is restaged
        }

        // ---- epilogue: bias + relu (+tf32 round) back into hA ----
#pragma unroll
        for (int mt = 0; mt < 2; mt++) {
            const int r0 = mbase + mt * 16 + lr;
#pragma unroll
            for (int nt = 0; nt < 8; nt++) {
                const int col = nbase + nt * 8 + 2 * lc;
                const float b0 = sbias[col], b1 = sbias[col + 1];
                float2 v01, v23;
                v01.x = tf32r(fmaxf(acc[mt][nt][0] + b0, 0.0f));
                v01.y = tf32r(fmaxf(acc[mt][nt][1] + b1, 0.0f));
                v23.x = tf32r(fmaxf(acc[mt][nt][2] + b0, 0.0f));
                v23.y = tf32r(fmaxf(acc[mt][nt][3] + b1, 0.0f));
                *(float2*)(hA + r0 * PADA + col) = v01;
                *(float2*)(hA + (r0 + 8) * PADA + col) = v23;
            }
        }
        __syncthreads();
    }

    // ---- column sums over 128 rows -> atomicAdd into g_xg ----
    {
        const int col = tid & 255;
        const int rh = tid >> 8;      // 0 or 1
        float s = 0.0f;
        const float* base = hA + rh * 64 * PADA + col;
#pragma unroll 8
        for (int r = 0; r < 64; r++) s += base[r * PADA];
        float* red = ws[0];
        red[rh * 256 + col] = s;
        __syncthreads();
        if (rh == 0) atomicAdd(&g_xg[b * H + col], red[col] + red[256 + col]);
    }
}

// =====================================================================
// Kernel 3: f-MLP + log_softmax
// =====================================================================
__global__ void k_f(const float* __restrict__ Wf1, const float* __restrict__ bf1,
                    const float* __restrict__ Wf2, const float* __restrict__ bf2,
                    const float* __restrict__ Wf3, const float* __restrict__ bf3,
                    float* __restrict__ out) {
    int b = blockIdx.x;
    int tid = threadIdx.x, lane = tid & 31, w = tid >> 5;

    __shared__ float xs[H], f1s[H], f2s[H], ls[32];

    xs[tid] = g_xg[b * H + tid];
    __syncthreads();

    for (int i = 0; i < 32; i++) {
        int n = w * 32 + i;
        float p = 0.0f;
#pragma unroll
        for (int j = 0; j < 8; j++) { int k = lane + 32 * j; p += xs[k] * Wf1[n * H + k]; }
#pragma unroll
        for (int off = 16; off > 0; off >>= 1) p += __shfl_xor_sync(0xffffffffu, p, off);
        if (lane == 0) f1s[n] = fmaxf(p + bf1[n], 0.0f);
    }
    __syncthreads();

    for (int i = 0; i < 32; i++) {
        int n = w * 32 + i;
        float p = 0.0f;
#pragma unroll
        for (int j = 0; j < 8; j++) { int k = lane + 32 * j; p += f1s[k] * Wf2[n * H + k]; }
#pragma unroll
        for (int off = 16; off > 0; off >>= 1) p += __shfl_xor_sync(0xffffffffu, p, off);
        if (lane == 0) f2s[n] = fmaxf(p + bf2[n], 0.0f);
    }
    __syncthreads();

    for (int i = 0; i < 4; i++) {
        int n = w * 4 + i;
        if (n < OUT) {
            float p = 0.0f;
#pragma unroll
            for (int j = 0; j < 8; j++) { int k = lane + 32 * j; p += f2s[k] * Wf3[n * H + k]; }
#pragma unroll
            for (int off = 16; off > 0; off >>= 1) p += __shfl_xor_sync(0xffffffffu, p, off);
            if (lane == 0) ls[n] = p + bf3[n];
        }
    }
    __syncthreads();

    if (w == 0) {
        float v = (lane < OUT) ? ls[lane] : -3.4e38f;
        float m = v;
#pragma unroll
        for (int off = 16; off > 0; off >>= 1) m = fmaxf(m, __shfl_xor_sync(0xffffffffu, m, off));
        float e = (lane < OUT) ? expf(v - m) : 0.0f;
        float s = e;
#pragma unroll
        for (int off = 16; off > 0; off >>= 1) s += __shfl_xor_sync(0xffffffffu, s, off);
        float lse = logf(s) + m;
        if (lane < OUT) out[b * OUT + lane] = v - lse;
    }
}

// =====================================================================
extern "C" void kernel_launch(void* const* d_in, const int* in_sizes, int n_in,
                              void* d_out, int out_size) {
    (void)in_sizes; (void)n_in; (void)out_size;
    const float* x   = (const float*)d_in[0];
    const float* qst = (const float*)d_in[1];
    const float* Wg1 = (const float*)d_in[2];
    const float* bg1 = (const float*)d_in[3];
    const float* Wg2 = (const float*)d_in[4];
    const float* bg2 = (const float*)d_in[5];
    const float* Wg3 = (const float*)d_in[6];
    const float* bg3 = (const float*)d_in[7];
    const float* Wg4 = (const float*)d_in[8];
    const float* bg4 = (const float*)d_in[9];
    const float* Wf1 = (const float*)d_in[10];
    const float* bf1 = (const float*)d_in[11];
    const float* Wf2 = (const float*)d_in[12];
    const float* bf2 = (const float*)d_in[13];
    const float* Wf3 = (const float*)d_in[14];
    const float* bf3 = (const float*)d_in[15];

    const size_t smem = (size_t)(256 + 128 * PADA + 2 * 256 * PADW) * sizeof(float); // ~206 KB
    cudaFuncSetAttribute(k_g, cudaFuncAttributeMaxDynamicSharedMemorySize, (int)smem);

    k_uv<<<dim3(MB, 4), 256>>>(x, qst, Wg1, bg1);
    k_g<<<dim3(S2 * S2 / 128, MB), NTHREADS, smem>>>(Wg2, bg2, Wg3, bg3, Wg4, bg4);
    k_f<<<MB, 256>>>(Wf1, bf1, Wf2, bf2, Wf3, bf3, (float*)d_out);
}

// round 9
// speedup vs baseline: 17.2209x; 2.6580x over previous
#include <cuda_runtime.h>
#include <cuda_bf16.h>
#include <cstdint>
#include <math.h>

#define MB   64
#define C    24
#define S2   64
#define QS   128
#define H    256
#define OUT  28

#define NTHREADS 512
#define PADH 264          // bf16 elems per hA row  (528 B)
#define PADWS 72          // bf16 elems per ws row  (144 B)
#define WSBYTES (256 * 144)

// smem byte offsets (k_g)
#define SB_BIAS 0
#define SB_GW   1024
#define SB_HA   2048
#define SB_WS   (2048 + 128 * 528)          // 69632
#define SB_TOTAL (SB_WS + 2 * WSBYTES)      // 143360

// ---------------- scratch ----------------
__device__ float g_u[MB * S2 * H];
__device__ float g_v[MB * S2 * H];
__device__ float g_w[MB * H];                       // qst-part + bias of layer 1
__device__ float g_xg[MB * H];
__device__ __align__(16) __nv_bfloat16 g_Wb[3 * H * H];   // bf16 weights

// ---------------- helpers ----------------
__device__ __forceinline__ uint32_t smem_u32(const void* p) {
    uint32_t a;
    asm("{ .reg .u64 t; cvta.to.shared.u64 t, %1; cvt.u32.u64 %0, t; }" : "=r"(a) : "l"(p));
    return a;
}
__device__ __forceinline__ void cp16(uint32_t dst, const void* src) {
    asm volatile("cp.async.ca.shared.global [%0], [%1], 16;" :: "r"(dst), "l"(src) : "memory");
}
__device__ __forceinline__ void cp_commit() {
    asm volatile("cp.async.commit_group;" ::: "memory");
}
__device__ __forceinline__ void ldm_x4(uint32_t* r, uint32_t addr) {
    asm volatile("ldmatrix.sync.aligned.m8n8.x4.shared.b16 {%0,%1,%2,%3}, [%4];"
                 : "=r"(r[0]), "=r"(r[1]), "=r"(r[2]), "=r"(r[3]) : "r"(addr));
}
__device__ __forceinline__ void mma_bf16(float* d, const uint32_t* a, const uint32_t* b) {
    asm volatile(
        "mma.sync.aligned.m16n8k16.row.col.f32.bf16.bf16.f32 "
        "{%0,%1,%2,%3}, {%4,%5,%6,%7}, {%8,%9}, {%0,%1,%2,%3};"
        : "+f"(d[0]), "+f"(d[1]), "+f"(d[2]), "+f"(d[3])
        : "r"(a[0]), "r"(a[1]), "r"(a[2]), "r"(a[3]), "r"(b[0]), "r"(b[1]));
}
__device__ __forceinline__ uint32_t bf2u(float a, float b) {
    __nv_bfloat162 h = __floats2bfloat162_rn(a, b);
    return *(uint32_t*)&h;
}

// =====================================================================
// k_wb: convert g-weights to bf16 once.  grid (64,3) x 256
// =====================================================================
__global__ void k_wb(const float* __restrict__ W2, const float* __restrict__ W3,
                     const float* __restrict__ W4) {
    const float* W = (blockIdx.y == 0) ? W2 : (blockIdx.y == 1) ? W3 : W4;
    __nv_bfloat16* dst = g_Wb + blockIdx.y * H * H;
    int i = (blockIdx.x * 256 + threadIdx.x) * 4;
    float4 v = *(const float4*)(W + i);
    uint2 o;
    o.x = bf2u(v.x, v.y);
    o.y = bf2u(v.z, v.w);
    *(uint2*)(dst + i) = o;
}

// =====================================================================
// k_qw: g_w[b][n] = qst[b] . Wg1[n][52:180] + bg1[n]   (coalesced, warp/row)
// =====================================================================
__global__ void k_qw(const float* __restrict__ qst, const float* __restrict__ Wg1,
                     const float* __restrict__ bg1) {
    int b = blockIdx.x;
    int tid = threadIdx.x, lane = tid & 31, w = tid >> 5;   // 8 warps
    __shared__ float qs[QS];
    if (tid < QS) qs[tid] = qst[b * QS + tid];
    __syncthreads();
    for (int i = 0; i < 32; i++) {
        int n = w * 32 + i;
        const float* wr = Wg1 + n * 180 + 52;
        float p = 0.0f;
#pragma unroll
        for (int j = 0; j < 4; j++) p += qs[lane + 32 * j] * wr[lane + 32 * j];
#pragma unroll
        for (int off = 16; off > 0; off >>= 1) p += __shfl_xor_sync(0xffffffffu, p, off);
        if (lane == 0) g_w[b * H + n] = p + bg1[n];
    }
}

// =====================================================================
// k_uv: u = xf.Wi, v = xf.Wj  (no qst part).  grid (MB,4)
// =====================================================================
__global__ void k_uv(const float* __restrict__ x, const float* __restrict__ Wg1) {
    int b = blockIdx.x, seg = blockIdx.y;
    int tid = threadIdx.x;

    __shared__ float xf[16][26];

    for (int i = tid; i < 16 * C; i += 256) {
        int c = i / 16, sl = i % 16;
        xf[sl][c] = x[(b * C + c) * S2 + seg * 16 + sl];
    }
    if (tid < 16) {
        int s = seg * 16 + tid;
        xf[tid][24] = ((s >> 3) - 4) * 0.25f;
        xf[tid][25] = ((s & 7) - 4) * 0.25f;
    }
    if (seg == 0) g_xg[b * H + tid] = 0.0f;
    __syncthreads();

    const int n = tid;
    const float* wr = Wg1 + n * 180;
    float Wi[26], Wj[26];
#pragma unroll
    for (int c = 0; c < 26; c++) { Wi[c] = wr[c]; Wj[c] = wr[26 + c]; }

    for (int sl = 0; sl < 16; sl++) {
        float su = 0.0f, sv = 0.0f;
#pragma unroll
        for (int c = 0; c < 26; c++) {
            float xv = xf[sl][c];
            su += xv * Wi[c];
            sv += xv * Wj[c];
        }
        int s = seg * 16 + sl;
        g_u[(b * S2 + s) * H + n] = su;
        g_v[(b * S2 + s) * H + n] = sv;
    }
}

// =====================================================================
// k_g: bf16 mma.sync g-MLP.  CTA = (batch, 2 p-rows): M=128,N=256,K=256.
//   16 warps: 4(m:32) x 4(n:64).  ldmatrix fragments, cp.async weights.
// =====================================================================
__global__ void __launch_bounds__(NTHREADS, 1)
k_g(const float* __restrict__ bg2, const float* __restrict__ bg3,
    const float* __restrict__ bg4) {
    extern __shared__ char smem[];
    float* sbias = (float*)(smem + SB_BIAS);
    float* sgw   = (float*)(smem + SB_GW);

    const int b = blockIdx.y, tile = blockIdx.x;
    const int tid = threadIdx.x, wid = tid >> 5, lane = tid & 31;
    const int mbase = (wid & 3) * 32;
    const int nbase = (wid >> 2) * 64;

    const uint32_t smA = smem_u32(smem + SB_HA);
    const uint32_t smW = smem_u32(smem + SB_WS);

    // per-lane ldmatrix address components
    const uint32_t aBase = smA + (uint32_t)(mbase + (lane & 15)) * 528 + (uint32_t)(lane >> 4) * 16;
    const uint32_t bOff  = (uint32_t)(((lane >> 4) * 8 + (lane & 7)) * 144 + ((lane >> 3) & 1) * 16);

    if (tid < H) sgw[tid] = g_w[b * H + tid];
    __syncthreads();

    // ---- build h1 = relu(u[q] + v[p] + w[n]) in bf16 ----
    const float* ub = g_u + b * S2 * H;
    const float* vb = g_v + b * S2 * H;
#pragma unroll
    for (int it = 0; it < 8; it++) {
        int i = tid + it * NTHREADS;           // 0..4095
        int r = i >> 5, kb = (i & 31) * 8;
        int q = r & 63, p = tile * 2 + (r >> 6);
        float4 u0 = *(const float4*)(ub + q * H + kb);
        float4 u1 = *(const float4*)(ub + q * H + kb + 4);
        float4 v0 = *(const float4*)(vb + p * H + kb);
        float4 v1 = *(const float4*)(vb + p * H + kb + 4);
        const float* w = sgw + kb;
        uint4 o;
        o.x = bf2u(fmaxf(u0.x + v0.x + w[0], 0.0f), fmaxf(u0.y + v0.y + w[1], 0.0f));
        o.y = bf2u(fmaxf(u0.z + v0.z + w[2], 0.0f), fmaxf(u0.w + v0.w + w[3], 0.0f));
        o.z = bf2u(fmaxf(u1.x + v1.x + w[4], 0.0f), fmaxf(u1.y + v1.y + w[5], 0.0f));
        o.w = bf2u(fmaxf(u1.z + v1.z + w[6], 0.0f), fmaxf(u1.w + v1.w + w[7], 0.0f));
        *(uint4*)(smem + SB_HA + r * 528 + kb * 2) = o;
    }

    const float* bl[3] = {bg2, bg3, bg4};

    for (int L = 0; L < 3; L++) {
        const __nv_bfloat16* Wb = g_Wb + L * H * H;
        if (tid < H) sbias[tid] = bl[L][tid];

        float acc[2][8][4];
#pragma unroll
        for (int mt = 0; mt < 2; mt++)
#pragma unroll
            for (int nt = 0; nt < 8; nt++)
#pragma unroll
                for (int i = 0; i < 4; i++) acc[mt][nt][i] = 0.0f;

        // stage chunk 0
        {
#pragma unroll
            for (int it = 0; it < 4; it++) {
                int idx = tid + it * NTHREADS;     // 0..2047
                int n = idx >> 3, q8 = idx & 7;
                cp16(smW + n * 144 + q8 * 16, Wb + n * H + q8 * 8);
            }
            cp_commit();
        }

        for (int c = 0; c < 4; c++) {              // K chunks of 64
            if (c < 3) {
                uint32_t dst = smW + ((c + 1) & 1) * WSBYTES;
                const __nv_bfloat16* src = Wb + (c + 1) * 64;
#pragma unroll
                for (int it = 0; it < 4; it++) {
                    int idx = tid + it * NTHREADS;
                    int n = idx >> 3, q8 = idx & 7;
                    cp16(dst + n * 144 + q8 * 16, src + n * H + q8 * 8);
                }
                cp_commit();
                asm volatile("cp.async.wait_group 1;" ::: "memory");
            } else {
                asm volatile("cp.async.wait_group 0;" ::: "memory");
            }
            __syncthreads();

            const uint32_t wbuf = smW + (c & 1) * WSBYTES;
#pragma unroll
            for (int kk = 0; kk < 4; kk++) {       // k16 steps
                const uint32_t kgA = (uint32_t)(c * 64 + kk * 16) * 2;
                uint32_t a[2][4], bf[8][2];
#pragma unroll
                for (int mt = 0; mt < 2; mt++)
                    ldm_x4(a[mt], aBase + (uint32_t)(mt * 16) * 528 + kgA);
#pragma unroll
                for (int i = 0; i < 4; i++) {
                    uint32_t r[4];
                    ldm_x4(r, wbuf + (uint32_t)(nbase + i * 16) * 144 + (uint32_t)(kk * 32) + bOff);
                    bf[2 * i][0] = r[0]; bf[2 * i][1] = r[1];
                    bf[2 * i + 1][0] = r[2]; bf[2 * i + 1][1] = r[3];
                }
#pragma unroll
                for (int mt = 0; mt < 2; mt++)
#pragma unroll
                    for (int nt = 0; nt < 8; nt++)
                        mma_bf16(acc[mt][nt], a[mt], bf[nt]);
            }
            __syncthreads();
        }

        if (L < 2) {
            // bias + relu -> bf16 back into hA
#pragma unroll
            for (int mt = 0; mt < 2; mt++) {
                const int r0 = mbase + mt * 16 + (lane >> 2);
#pragma unroll
                for (int nt = 0; nt < 8; nt++) {
                    const int col = nbase + nt * 8 + 2 * (lane & 3);
                    const float b0 = sbias[col], b1 = sbias[col + 1];
                    *(uint32_t*)(smem + SB_HA + r0 * 528 + col * 2) =
                        bf2u(fmaxf(acc[mt][nt][0] + b0, 0.0f), fmaxf(acc[mt][nt][1] + b1, 0.0f));
                    *(uint32_t*)(smem + SB_HA + (r0 + 8) * 528 + col * 2) =
                        bf2u(fmaxf(acc[mt][nt][2] + b0, 0.0f), fmaxf(acc[mt][nt][3] + b1, 0.0f));
                }
            }
            __syncthreads();
        } else {
            // layer 4: relu + column sums -> atomicAdd
            float* red = (float*)(smem + SB_WS);   // [4][256]
#pragma unroll
            for (int nt = 0; nt < 8; nt++) {
                const int col = nbase + nt * 8 + 2 * (lane & 3);
                const float b0 = sbias[col], b1 = sbias[col + 1];
                float s0 = 0.0f, s1 = 0.0f;
#pragma unroll
                for (int mt = 0; mt < 2; mt++) {
                    s0 += fmaxf(acc[mt][nt][0] + b0, 0.0f) + fmaxf(acc[mt][nt][2] + b0, 0.0f);
                    s1 += fmaxf(acc[mt][nt][1] + b1, 0.0f) + fmaxf(acc[mt][nt][3] + b1, 0.0f);
                }
#pragma unroll
                for (int off = 4; off <= 16; off <<= 1) {
                    s0 += __shfl_xor_sync(0xffffffffu, s0, off);
                    s1 += __shfl_xor_sync(0xffffffffu, s1, off);
                }
                if (lane < 4) {
                    red[(wid & 3) * H + col] = s0;
                    red[(wid & 3) * H + col + 1] = s1;
                }
            }
            __syncthreads();
            if (tid < H) {
                float tot = red[tid] + red[H + tid] + red[2 * H + tid] + red[3 * H + tid];
                atomicAdd(&g_xg[b * H + tid], tot);
            }
        }
    }
}

// =====================================================================
// k_f: f-MLP + log_softmax
// =====================================================================
__global__ void k_f(const float* __restrict__ Wf1, const float* __restrict__ bf1,
                    const float* __restrict__ Wf2, const float* __restrict__ bf2,
                    const float* __restrict__ Wf3, const float* __restrict__ bf3,
                    float* __restrict__ out) {
    int b = blockIdx.x;
    int tid = threadIdx.x, lane = tid & 31, w = tid >> 5;

    __shared__ float xs[H], f1s[H], f2s[H], ls[32];

    xs[tid] = g_xg[b * H + tid];
    __syncthreads();

    for (int i = 0; i < 32; i++) {
        int n = w * 32 + i;
        float p = 0.0f;
#pragma unroll
        for (int j = 0; j < 8; j++) { int k = lane + 32 * j; p += xs[k] * Wf1[n * H + k]; }
#pragma unroll
        for (int off = 16; off > 0; off >>= 1) p += __shfl_xor_sync(0xffffffffu, p, off);
        if (lane == 0) f1s[n] = fmaxf(p + bf1[n], 0.0f);
    }
    __syncthreads();

    for (int i = 0; i < 32; i++) {
        int n = w * 32 + i;
        float p = 0.0f;
#pragma unroll
        for (int j = 0; j < 8; j++) { int k = lane + 32 * j; p += f1s[k] * Wf2[n * H + k]; }
#pragma unroll
        for (int off = 16; off > 0; off >>= 1) p += __shfl_xor_sync(0xffffffffu, p, off);
        if (lane == 0) f2s[n] = fmaxf(p + bf2[n], 0.0f);
    }
    __syncthreads();

    for (int i = 0; i < 4; i++) {
        int n = w * 4 + i;
        if (n < OUT) {
            float p = 0.0f;
#pragma unroll
            for (int j = 0; j < 8; j++) { int k = lane + 32 * j; p += f2s[k] * Wf3[n * H + k]; }
#pragma unroll
            for (int off = 16; off > 0; off >>= 1) p += __shfl_xor_sync(0xffffffffu, p, off);
            if (lane == 0) ls[n] = p + bf3[n];
        }
    }
    __syncthreads();

    if (w == 0) {
        float v = (lane < OUT) ? ls[lane] : -3.4e38f;
        float m = v;
#pragma unroll
        for (int off = 16; off > 0; off >>= 1) m = fmaxf(m, __shfl_xor_sync(0xffffffffu, m, off));
        float e = (lane < OUT) ? expf(v - m) : 0.0f;
        float s = e;
#pragma unroll
        for (int off = 16; off > 0; off >>= 1) s += __shfl_xor_sync(0xffffffffu, s, off);
        float lse = logf(s) + m;
        if (lane < OUT) out[b * OUT + lane] = v - lse;
    }
}

// =====================================================================
extern "C" void kernel_launch(void* const* d_in, const int* in_sizes, int n_in,
                              void* d_out, int out_size) {
    (void)in_sizes; (void)n_in; (void)out_size;
    const float* x   = (const float*)d_in[0];
    const float* qst = (const float*)d_in[1];
    const float* Wg1 = (const float*)d_in[2];
    const float* bg1 = (const float*)d_in[3];
    const float* Wg2 = (const float*)d_in[4];
    const float* bg2 = (const float*)d_in[5];
    const float* Wg3 = (const float*)d_in[6];
    const float* bg3 = (const float*)d_in[7];
    const float* Wg4 = (const float*)d_in[8];
    const float* bg4 = (const float*)d_in[9];
    const float* Wf1 = (const float*)d_in[10];
    const float* bf1 = (const float*)d_in[11];
    const float* Wf2 = (const float*)d_in[12];
    const float* bf2 = (const float*)d_in[13];
    const float* Wf3 = (const float*)d_in[14];
    const float* bf3 = (const float*)d_in[15];

    cudaFuncSetAttribute(k_g, cudaFuncAttributeMaxDynamicSharedMemorySize, SB_TOTAL);

    k_wb<<<dim3(64, 3), 256>>>(Wg2, Wg3, Wg4);
    k_qw<<<MB, 256>>>(qst, Wg1, bg1);
    k_uv<<<dim3(MB, 4), 256>>>(x, Wg1);
    k_g<<<dim3(S2 * S2 / 128, MB), NTHREADS, SB_TOTAL>>>(bg2, bg3, bg4);
    k_f<<<MB, 256>>>(Wf1, bf1, Wf2, bf2, Wf3, bf3, (float*)d_out);
}

// round 10
// speedup vs baseline: 17.9608x; 1.0430x over previous
#include <cuda_runtime.h>
#include <cuda_bf16.h>
#include <cstdint>
#include <math.h>

#define MB   64
#define C    24
#define S2   64
#define QS   128
#define H    256
#define OUT  28

#define NTHREADS 512

// k_g smem layout (bytes)
#define SB_BIAS  0                       // 3*256 floats = 3072
#define SB_HA    3072                    // 128 * 528    = 67584
#define SB_WS    70656                   // 3 * 36864    = 110592
#define SB_TOTAL 181248
#define WSLAB    36864                   // one K64 chunk: 256 rows * 144 B

// ---------------- scratch ----------------
__device__ float g_u[MB * S2 * H];
__device__ float g_v[MB * S2 * H];
__device__ float g_w[MB * H];
__device__ float g_xg[MB * H];
__device__ __align__(16) __nv_bfloat16 g_Wb[3 * H * H];

// ---------------- helpers ----------------
__device__ __forceinline__ uint32_t smem_u32(const void* p) {
    uint32_t a;
    asm("{ .reg .u64 t; cvta.to.shared.u64 t, %1; cvt.u32.u64 %0, t; }" : "=r"(a) : "l"(p));
    return a;
}
__device__ __forceinline__ void cp16(uint32_t dst, const void* src) {
    asm volatile("cp.async.ca.shared.global [%0], [%1], 16;" :: "r"(dst), "l"(src) : "memory");
}
__device__ __forceinline__ void cp_commit() {
    asm volatile("cp.async.commit_group;" ::: "memory");
}
__device__ __forceinline__ void ldm_x4(uint32_t* r, uint32_t addr) {
    asm volatile("ldmatrix.sync.aligned.m8n8.x4.shared.b16 {%0,%1,%2,%3}, [%4];"
                 : "=r"(r[0]), "=r"(r[1]), "=r"(r[2]), "=r"(r[3]) : "r"(addr));
}
__device__ __forceinline__ void mma_bf16(float* d, const uint32_t* a, const uint32_t* b) {
    asm volatile(
        "mma.sync.aligned.m16n8k16.row.col.f32.bf16.bf16.f32 "
        "{%0,%1,%2,%3}, {%4,%5,%6,%7}, {%8,%9}, {%0,%1,%2,%3};"
        : "+f"(d[0]), "+f"(d[1]), "+f"(d[2]), "+f"(d[3])
        : "r"(a[0]), "r"(a[1]), "r"(a[2]), "r"(a[3]), "r"(b[0]), "r"(b[1]));
}
__device__ __forceinline__ uint32_t bf2u(float a, float b) {
    __nv_bfloat162 h = __floats2bfloat162_rn(a, b);
    return *(uint32_t*)&h;
}

// =====================================================================
// k_prep: fused  [0,192): W->bf16   [192,256): qw   [256,512): uv
// =====================================================================
__global__ void k_prep(const float* __restrict__ x, const float* __restrict__ qst,
                       const float* __restrict__ Wg1, const float* __restrict__ bg1,
                       const float* __restrict__ W2, const float* __restrict__ W3,
                       const float* __restrict__ W4) {
    const int bid = blockIdx.x, tid = threadIdx.x;

    if (bid < 192) {                       // ---- weight convert ----
        int l = bid >> 6, blk = bid & 63;
        const float* W = (l == 0) ? W2 : (l == 1) ? W3 : W4;
        int i = (blk * 256 + tid) * 4;
        float4 v = *(const float4*)(W + i);
        uint2 o;
        o.x = bf2u(v.x, v.y);
        o.y = bf2u(v.z, v.w);
        *(uint2*)(g_Wb + l * H * H + i) = o;
        return;
    }
    if (bid < 256) {                       // ---- qw ----
        int b = bid - 192;
        int lane = tid & 31, w = tid >> 5;
        __shared__ float qs[QS];
        if (tid < QS) qs[tid] = qst[b * QS + tid];
        __syncthreads();
        for (int i = 0; i < 32; i++) {
            int n = w * 32 + i;
            const float* wr = Wg1 + n * 180 + 52;
            float p = 0.0f;
#pragma unroll
            for (int j = 0; j < 4; j++) p += qs[lane + 32 * j] * wr[lane + 32 * j];
#pragma unroll
            for (int off = 16; off > 0; off >>= 1) p += __shfl_xor_sync(0xffffffffu, p, off);
            if (lane == 0) g_w[b * H + n] = p + bg1[n];
        }
        return;
    }
    // ---- uv ----
    {
        int idx = bid - 256;
        int b = idx >> 2, seg = idx & 3;
        __shared__ float xf[16][26];
        for (int i = tid; i < 16 * C; i += 256) {
            int c = i / 16, sl = i % 16;
            xf[sl][c] = x[(b * C + c) * S2 + seg * 16 + sl];
        }
        if (tid < 16) {
            int s = seg * 16 + tid;
            xf[tid][24] = ((s >> 3) - 4) * 0.25f;
            xf[tid][25] = ((s & 7) - 4) * 0.25f;
        }
        if (seg == 0) g_xg[b * H + tid] = 0.0f;
        __syncthreads();

        const int n = tid;
        const float* wr = Wg1 + n * 180;
        float Wi[26], Wj[26];
#pragma unroll
        for (int c = 0; c < 26; c++) { Wi[c] = wr[c]; Wj[c] = wr[26 + c]; }
        for (int sl = 0; sl < 16; sl++) {
            float su = 0.0f, sv = 0.0f;
#pragma unroll
            for (int c = 0; c < 26; c++) {
                float xv = xf[sl][c];
                su += xv * Wi[c];
                sv += xv * Wj[c];
            }
            int s = seg * 16 + sl;
            g_u[(b * S2 + s) * H + n] = su;
            g_v[(b * S2 + s) * H + n] = sv;
        }
    }
}

// =====================================================================
// k_g: bf16 mma.sync g-MLP.  CTA = (batch, 2 p-rows): M=128,N=256,K=256.
//   16 warps 4(m)x4(n).  Per-n-group weight staging + named barriers;
//   triple-buffered cp.async stream over all 12 K-chunks.
// =====================================================================
__global__ void __launch_bounds__(NTHREADS, 1)
k_g(const float* __restrict__ bg2, const float* __restrict__ bg3,
    const float* __restrict__ bg4) {
    extern __shared__ char smem[];
    float* sbias = (float*)(smem + SB_BIAS);

    const int b = blockIdx.y, tile = blockIdx.x;
    const int tid = threadIdx.x, wid = tid >> 5, lane = tid & 31;
    const int mbase = (wid & 3) * 32;
    const int ng   = wid >> 2;              // n-group 0..3
    const int nbase = ng * 64;
    const int wtid = tid & 127;             // thread-in-group

    const uint32_t smA = smem_u32(smem + SB_HA);
    const uint32_t smW = smem_u32(smem + SB_WS);

    const uint32_t aBase = smA + (uint32_t)(mbase + (lane & 15)) * 528 + (uint32_t)(lane >> 4) * 16;
    const uint32_t bOff  = (uint32_t)(((lane >> 4) * 8 + (lane & 7)) * 144 + ((lane >> 3) & 1) * 16);

    // stage all 3 biases (visible after first pre-epilogue __syncthreads)
    if (tid < 256) {
        sbias[tid]       = bg2[tid];
        sbias[256 + tid] = bg3[tid];
        sbias[512 + tid] = bg4[tid];
    }

    // ---- weight staging (per n-group slab: rows [ng*64, ng*64+64)) ----
    auto stage = [&](int c) {
        const int L = c >> 2, kc = c & 3;
        const __nv_bfloat16* Wb = g_Wb + L * H * H + kc * 64;
        const uint32_t dst = smW + (uint32_t)(c % 3) * WSLAB;
#pragma unroll
        for (int it = 0; it < 4; it++) {
            int idx = wtid + it * 128;       // 0..511
            int nl = idx >> 3, k8 = idx & 7;
            int n = nbase + nl;
            cp16(dst + (uint32_t)(n * 144 + k8 * 16), Wb + n * H + k8 * 8);
        }
        cp_commit();
    };

    stage(0);
    stage(1);

    // ---- build h1 = relu(u[q] + v[p] + w[n]) in bf16 (overlaps cp.async) ----
    const float* ub = g_u + b * S2 * H;
    const float* vb = g_v + b * S2 * H;
    const float* wb_ = g_w + b * H;
#pragma unroll
    for (int it = 0; it < 8; it++) {
        int i = tid + it * NTHREADS;
        int r = i >> 5, kb = (i & 31) * 8;
        int q = r & 63, p = tile * 2 + (r >> 6);
        float4 u0 = *(const float4*)(ub + q * H + kb);
        float4 u1 = *(const float4*)(ub + q * H + kb + 4);
        float4 v0 = *(const float4*)(vb + p * H + kb);
        float4 v1 = *(const float4*)(vb + p * H + kb + 4);
        float4 w0 = *(const float4*)(wb_ + kb);
        float4 w1 = *(const float4*)(wb_ + kb + 4);
        uint4 o;
        o.x = bf2u(fmaxf(u0.x + v0.x + w0.x, 0.0f), fmaxf(u0.y + v0.y + w0.y, 0.0f));
        o.y = bf2u(fmaxf(u0.z + v0.z + w0.z, 0.0f), fmaxf(u0.w + v0.w + w0.w, 0.0f));
        o.z = bf2u(fmaxf(u1.x + v1.x + w1.x, 0.0f), fmaxf(u1.y + v1.y + w1.y, 0.0f));
        o.w = bf2u(fmaxf(u1.z + v1.z + w1.z, 0.0f), fmaxf(u1.w + v1.w + w1.w, 0.0f));
        *(uint4*)(smem + SB_HA + r * 528 + kb * 2) = o;
    }
    // hA written by all threads, read cross-warp within m-groups -> one barrier
    __syncthreads();

    float acc[2][8][4];
#pragma unroll
    for (int mt = 0; mt < 2; mt++)
#pragma unroll
        for (int nt = 0; nt < 8; nt++)
#pragma unroll
            for (int i = 0; i < 4; i++) acc[mt][nt][i] = 0.0f;

    for (int c = 0; c < 12; c++) {
        const int kc = c & 3;

        if (c + 2 < 12) stage(c + 2);
        // chunk c's cp.async group must be complete (groups retire in order)
        if (c <= 9)      { asm volatile("cp.async.wait_group 2;" ::: "memory"); }
        else if (c == 10){ asm volatile("cp.async.wait_group 1;" ::: "memory"); }
        else             { asm volatile("cp.async.wait_group 0;" ::: "memory"); }
        // group-local visibility barrier (staging threads == reading threads' group)
        asm volatile("bar.sync %0, 128;" :: "r"(ng + 1) : "memory");

        const uint32_t wbuf = smW + (uint32_t)(c % 3) * WSLAB;
#pragma unroll
        for (int kk = 0; kk < 4; kk++) {
            const uint32_t kgA = (uint32_t)(kc * 64 + kk * 16) * 2;
            uint32_t a[2][4], bf[8][2];
#pragma unroll
            for (int mt = 0; mt < 2; mt++)
                ldm_x4(a[mt], aBase + (uint32_t)(mt * 16) * 528 + kgA);
#pragma unroll
            for (int i = 0; i < 4; i++) {
                uint32_t r[4];
                ldm_x4(r, wbuf + (uint32_t)(nbase + i * 16) * 144 + (uint32_t)(kk * 32) + bOff);
                bf[2 * i][0] = r[0]; bf[2 * i][1] = r[1];
                bf[2 * i + 1][0] = r[2]; bf[2 * i + 1][1] = r[3];
            }
#pragma unroll
            for (int mt = 0; mt < 2; mt++)
#pragma unroll
                for (int nt = 0; nt < 8; nt++)
                    mma_bf16(acc[mt][nt], a[mt], bf[nt]);
        }

        if (kc == 3) {          // ---- layer boundary ----
            const int L = c >> 2;
            const float* sb = sbias + L * 256;
            if (L < 2) {
                __syncthreads();   // all reads of hA (layer L) complete
#pragma unroll
                for (int mt = 0; mt < 2; mt++) {
                    const int r0 = mbase + mt * 16 + (lane >> 2);
#pragma unroll
                    for (int nt = 0; nt < 8; nt++) {
                        const int col = nbase + nt * 8 + 2 * (lane & 3);
                        const float b0 = sb[col], b1 = sb[col + 1];
                        *(uint32_t*)(smem + SB_HA + r0 * 528 + col * 2) =
                            bf2u(fmaxf(acc[mt][nt][0] + b0, 0.0f), fmaxf(acc[mt][nt][1] + b1, 0.0f));
                        *(uint32_t*)(smem + SB_HA + (r0 + 8) * 528 + col * 2) =
                            bf2u(fmaxf(acc[mt][nt][2] + b0, 0.0f), fmaxf(acc[mt][nt][3] + b1, 0.0f));
                    }
                }
#pragma unroll
                for (int mt = 0; mt < 2; mt++)
#pragma unroll
                    for (int nt = 0; nt < 8; nt++)
#pragma unroll
                        for (int i = 0; i < 4; i++) acc[mt][nt][i] = 0.0f;
                __syncthreads();   // hA(L+1) visible before reads
            } else {
                // layer 4: relu + column sums -> atomicAdd
                __syncthreads();   // everyone done with smem reads
                float* red = (float*)(smem + SB_WS);
#pragma unroll
                for (int nt = 0; nt < 8; nt++) {
                    const int col = nbase + nt * 8 + 2 * (lane & 3);
                    const float b0 = sb[col], b1 = sb[col + 1];
                    float s0 = 0.0f, s1 = 0.0f;
#pragma unroll
                    for (int mt = 0; mt < 2; mt++) {
                        s0 += fmaxf(acc[mt][nt][0] + b0, 0.0f) + fmaxf(acc[mt][nt][2] + b0, 0.0f);
                        s1 += fmaxf(acc[mt][nt][1] + b1, 0.0f) + fmaxf(acc[mt][nt][3] + b1, 0.0f);
                    }
#pragma unroll
                    for (int off = 4; off <= 16; off <<= 1) {
                        s0 += __shfl_xor_sync(0xffffffffu, s0, off);
                        s1 += __shfl_xor_sync(0xffffffffu, s1, off);
                    }
                    if (lane < 4) {
                        red[(wid & 3) * H + col] = s0;
                        red[(wid & 3) * H + col + 1] = s1;
                    }
                }
                __syncthreads();
                if (tid < H) {
                    float tot = red[tid] + red[H + tid] + red[2 * H + tid] + red[3 * H + tid];
                    atomicAdd(&g_xg[b * H + tid], tot);
                }
            }
        }
    }
}

// =====================================================================
// k_f: f-MLP + log_softmax
// =====================================================================
__global__ void k_f(const float* __restrict__ Wf1, const float* __restrict__ bf1,
                    const float* __restrict__ Wf2, const float* __restrict__ bf2,
                    const float* __restrict__ Wf3, const float* __restrict__ bf3,
                    float* __restrict__ out) {
    int b = blockIdx.x;
    int tid = threadIdx.x, lane = tid & 31, w = tid >> 5;

    __shared__ float xs[H], f1s[H], f2s[H], ls[32];

    xs[tid] = g_xg[b * H + tid];
    __syncthreads();

    for (int i = 0; i < 32; i++) {
        int n = w * 32 + i;
        float p = 0.0f;
#pragma unroll
        for (int j = 0; j < 8; j++) { int k = lane + 32 * j; p += xs[k] * Wf1[n * H + k]; }
#pragma unroll
        for (int off = 16; off > 0; off >>= 1) p += __shfl_xor_sync(0xffffffffu, p, off);
        if (lane == 0) f1s[n] = fmaxf(p + bf1[n], 0.0f);
    }
    __syncthreads();

    for (int i = 0; i < 32; i++) {
        int n = w * 32 + i;
        float p = 0.0f;
#pragma unroll
        for (int j = 0; j < 8; j++) { int k = lane + 32 * j; p += f1s[k] * Wf2[n * H + k]; }
#pragma unroll
        for (int off = 16; off > 0; off >>= 1) p += __shfl_xor_sync(0xffffffffu, p, off);
        if (lane == 0) f2s[n] = fmaxf(p + bf2[n], 0.0f);
    }
    __syncthreads();

    for (int i = 0; i < 4; i++) {
        int n = w * 4 + i;
        if (n < OUT) {
            float p = 0.0f;
#pragma unroll
            for (int j = 0; j < 8; j++) { int k = lane + 32 * j; p += f2s[k] * Wf3[n * H + k]; }
#pragma unroll
            for (int off = 16; off > 0; off >>= 1) p += __shfl_xor_sync(0xffffffffu, p, off);
            if (lane == 0) ls[n] = p + bf3[n];
        }
    }
    __syncthreads();

    if (w == 0) {
        float v = (lane < OUT) ? ls[lane] : -3.4e38f;
        float m = v;
#pragma unroll
        for (int off = 16; off > 0; off >>= 1) m = fmaxf(m, __shfl_xor_sync(0xffffffffu, m, off));
        float e = (lane < OUT) ? expf(v - m) : 0.0f;
        float s = e;
#pragma unroll
        for (int off = 16; off > 0; off >>= 1) s += __shfl_xor_sync(0xffffffffu, s, off);
        float lse = logf(s) + m;
        if (lane < OUT) out[b * OUT + lane] = v - lse;
    }
}

// =====================================================================
extern "C" void kernel_launch(void* const* d_in, const int* in_sizes, int n_in,
                              void* d_out, int out_size) {
    (void)in_sizes; (void)n_in; (void)out_size;
    const float* x   = (const float*)d_in[0];
    const float* qst = (const float*)d_in[1];
    const float* Wg1 = (const float*)d_in[2];
    const float* bg1 = (const float*)d_in[3];
    const float* Wg2 = (const float*)d_in[4];
    const float* bg2 = (const float*)d_in[5];
    const float* Wg3 = (const float*)d_in[6];
    const float* bg3 = (const float*)d_in[7];
    const float* Wg4 = (const float*)d_in[8];
    const float* bg4 = (const float*)d_in[9];
    const float* Wf1 = (const float*)d_in[10];
    const float* bf1 = (const float*)d_in[11];
    const float* Wf2 = (const float*)d_in[12];
    const float* bf2 = (const float*)d_in[13];
    const float* Wf3 = (const float*)d_in[14];
    const float* bf3 = (const float*)d_in[15];

    cudaFuncSetAttribute(k_g, cudaFuncAttributeMaxDynamicSharedMemorySize, SB_TOTAL);

    k_prep<<<512, 256>>>(x, qst, Wg1, bg1, Wg2, Wg3, Wg4);
    k_g<<<dim3(S2 * S2 / 128, MB), NTHREADS, SB_TOTAL>>>(bg2, bg3, bg4);
    k_f<<<MB, 256>>>(Wf1, bf1, Wf2, bf2, Wf3, bf3, (float*)d_out);
}

// round 11
// speedup vs baseline: 18.0744x; 1.0063x over previous
#include <cuda_runtime.h>
#include <cuda_bf16.h>
#include <cstdint>
#include <math.h>

#define MB   64
#define C    24
#define S2   64
#define QS   128
#define H    256
#define OUT  28

#define NTHREADS 256

// k_g smem layout (bytes)
#define SB_BIAS  0                       // 3*256 floats = 3072
#define SB_HA    3072                    // 64 * 528     = 33792
#define SB_WS    36864                   // 2 * 36864    = 73728
#define SB_TOTAL 110592                  // 108 KB -> 2 CTAs/SM
#define WSLAB    36864                   // one K64 chunk: 256 rows * 144 B

// ---------------- scratch ----------------
__device__ float g_u[MB * S2 * H];
__device__ float g_v[MB * S2 * H];
__device__ float g_w[MB * H];
__device__ float g_xg[MB * H];
__device__ __align__(16) __nv_bfloat16 g_Wb[3 * H * H];

// ---------------- helpers ----------------
__device__ __forceinline__ uint32_t smem_u32(const void* p) {
    uint32_t a;
    asm("{ .reg .u64 t; cvta.to.shared.u64 t, %1; cvt.u32.u64 %0, t; }" : "=r"(a) : "l"(p));
    return a;
}
__device__ __forceinline__ void cp16(uint32_t dst, const void* src) {
    asm volatile("cp.async.ca.shared.global [%0], [%1], 16;" :: "r"(dst), "l"(src) : "memory");
}
__device__ __forceinline__ void cp_commit() {
    asm volatile("cp.async.commit_group;" ::: "memory");
}
__device__ __forceinline__ void ldm_x4(uint32_t* r, uint32_t addr) {
    asm volatile("ldmatrix.sync.aligned.m8n8.x4.shared.b16 {%0,%1,%2,%3}, [%4];"
                 : "=r"(r[0]), "=r"(r[1]), "=r"(r[2]), "=r"(r[3]) : "r"(addr));
}
__device__ __forceinline__ void mma_bf16(float* d, const uint32_t* a, const uint32_t* b) {
    asm volatile(
        "mma.sync.aligned.m16n8k16.row.col.f32.bf16.bf16.f32 "
        "{%0,%1,%2,%3}, {%4,%5,%6,%7}, {%8,%9}, {%0,%1,%2,%3};"
        : "+f"(d[0]), "+f"(d[1]), "+f"(d[2]), "+f"(d[3])
        : "r"(a[0]), "r"(a[1]), "r"(a[2]), "r"(a[3]), "r"(b[0]), "r"(b[1]));
}
__device__ __forceinline__ uint32_t bf2u(float a, float b) {
    __nv_bfloat162 h = __floats2bfloat162_rn(a, b);
    return *(uint32_t*)&h;
}

// =====================================================================
// k_prep: fused  [0,192): W->bf16   [192,256): qw   [256,512): uv
// =====================================================================
__global__ void k_prep(const float* __restrict__ x, const float* __restrict__ qst,
                       const float* __restrict__ Wg1, const float* __restrict__ bg1,
                       const float* __restrict__ W2, const float* __restrict__ W3,
                       const float* __restrict__ W4) {
    const int bid = blockIdx.x, tid = threadIdx.x;

    if (bid < 192) {
        int l = bid >> 6, blk = bid & 63;
        const float* W = (l == 0) ? W2 : (l == 1) ? W3 : W4;
        int i = (blk * 256 + tid) * 4;
        float4 v = *(const float4*)(W + i);
        uint2 o;
        o.x = bf2u(v.x, v.y);
        o.y = bf2u(v.z, v.w);
        *(uint2*)(g_Wb + l * H * H + i) = o;
        return;
    }
    if (bid < 256) {
        int b = bid - 192;
        int lane = tid & 31, w = tid >> 5;
        __shared__ float qs[QS];
        if (tid < QS) qs[tid] = qst[b * QS + tid];
        __syncthreads();
        for (int i = 0; i < 32; i++) {
            int n = w * 32 + i;
            const float* wr = Wg1 + n * 180 + 52;
            float p = 0.0f;
#pragma unroll
            for (int j = 0; j < 4; j++) p += qs[lane + 32 * j] * wr[lane + 32 * j];
#pragma unroll
            for (int off = 16; off > 0; off >>= 1) p += __shfl_xor_sync(0xffffffffu, p, off);
            if (lane == 0) g_w[b * H + n] = p + bg1[n];
        }
        return;
    }
    {
        int idx = bid - 256;
        int b = idx >> 2, seg = idx & 3;
        __shared__ float xf[16][26];
        for (int i = tid; i < 16 * C; i += 256) {
            int c = i / 16, sl = i % 16;
            xf[sl][c] = x[(b * C + c) * S2 + seg * 16 + sl];
        }
        if (tid < 16) {
            int s = seg * 16 + tid;
            xf[tid][24] = ((s >> 3) - 4) * 0.25f;
            xf[tid][25] = ((s & 7) - 4) * 0.25f;
        }
        if (seg == 0) g_xg[b * H + tid] = 0.0f;
        __syncthreads();

        const int n = tid;
        const float* wr = Wg1 + n * 180;
        float Wi[26], Wj[26];
#pragma unroll
        for (int c = 0; c < 26; c++) { Wi[c] = wr[c]; Wj[c] = wr[26 + c]; }
        for (int sl = 0; sl < 16; sl++) {
            float su = 0.0f, sv = 0.0f;
#pragma unroll
            for (int c = 0; c < 26; c++) {
                float xv = xf[sl][c];
                su += xv * Wi[c];
                sv += xv * Wj[c];
            }
            int s = seg * 16 + sl;
            g_u[(b * S2 + s) * H + n] = su;
            g_v[(b * S2 + s) * H + n] = sv;
        }
    }
}

// =====================================================================
// k_g: bf16 mma.sync g-MLP.  CTA = (p-row, batch): M=64,N=256,K=256.
//   8 warps 2(m:32) x 4(n:64).  256 threads, 2 CTAs/SM.
//   Double-buffered K64 weight slabs, per-n-group staging + named barriers.
// =====================================================================
__global__ void __launch_bounds__(NTHREADS, 2)
k_g(const float* __restrict__ bg2, const float* __restrict__ bg3,
    const float* __restrict__ bg4) {
    extern __shared__ char smem[];
    float* sbias = (float*)(smem + SB_BIAS);

    const int b = blockIdx.y, p = blockIdx.x;      // p-row 0..63
    const int tid = threadIdx.x, wid = tid >> 5, lane = tid & 31;
    const int mbase = (wid & 1) * 32;
    const int ng = wid >> 1;                       // n-group 0..3 (2 warps each)
    const int nbase = ng * 64;
    const int wtid = tid & 63;                     // thread-in-group

    const uint32_t smA = smem_u32(smem + SB_HA);
    const uint32_t smW = smem_u32(smem + SB_WS);

    const uint32_t aBase = smA + (uint32_t)(mbase + (lane & 15)) * 528 + (uint32_t)(lane >> 4) * 16;
    const uint32_t bOff  = (uint32_t)(((lane >> 4) * 8 + (lane & 7)) * 144 + ((lane >> 3) & 1) * 16);

    if (tid < 256) {
        sbias[tid]       = bg2[tid];
        sbias[256 + tid] = bg3[tid];
        sbias[512 + tid] = bg4[tid];
    }

    // stage chunk c into slab c&1 (per n-group rows [nbase, nbase+64))
    auto stage = [&](int c) {
        const int L = c >> 2, kc = c & 3;
        const __nv_bfloat16* Wb = g_Wb + L * H * H + kc * 64;
        const uint32_t dst = smW + (uint32_t)(c & 1) * WSLAB;
#pragma unroll
        for (int it = 0; it < 8; it++) {
            int idx = wtid + it * 64;              // 0..511
            int nl = idx >> 3, k8 = idx & 7;
            int n = nbase + nl;
            cp16(dst + (uint32_t)(n * 144 + k8 * 16), Wb + n * H + k8 * 8);
        }
        cp_commit();
    };

    stage(0);
    stage(1);

    // ---- build h1 = relu(u[q] + v[p] + w[n]) in bf16 (M=64 rows) ----
    const float* ub = g_u + b * S2 * H;
    const float* vp = g_v + (b * S2 + p) * H;
    const float* wb_ = g_w + b * H;
#pragma unroll
    for (int it = 0; it < 8; it++) {
        int i = tid + it * NTHREADS;               // 0..2047
        int q = i >> 5, kb = (i & 31) * 8;
        float4 u0 = *(const float4*)(ub + q * H + kb);
        float4 u1 = *(const float4*)(ub + q * H + kb + 4);
        float4 v0 = *(const float4*)(vp + kb);
        float4 v1 = *(const float4*)(vp + kb + 4);
        float4 w0 = *(const float4*)(wb_ + kb);
        float4 w1 = *(const float4*)(wb_ + kb + 4);
        uint4 o;
        o.x = bf2u(fmaxf(u0.x + v0.x + w0.x, 0.0f), fmaxf(u0.y + v0.y + w0.y, 0.0f));
        o.y = bf2u(fmaxf(u0.z + v0.z + w0.z, 0.0f), fmaxf(u0.w + v0.w + w0.w, 0.0f));
        o.z = bf2u(fmaxf(u1.x + v1.x + w1.x, 0.0f), fmaxf(u1.y + v1.y + w1.y, 0.0f));
        o.w = bf2u(fmaxf(u1.z + v1.z + w1.z, 0.0f), fmaxf(u1.w + v1.w + w1.w, 0.0f));
        *(uint4*)(smem + SB_HA + q * 528 + kb * 2) = o;
    }
    __syncthreads();

    float acc[2][8][4];
#pragma unroll
    for (int mt = 0; mt < 2; mt++)
#pragma unroll
        for (int nt = 0; nt < 8; nt++)
#pragma unroll
            for (int i = 0; i < 4; i++) acc[mt][nt][i] = 0.0f;

    for (int c = 0; c < 12; c++) {
        const int kc = c & 3;

        // chunk c staged & visible (commits retire in order; c+1 may be pending)
        if (c <= 10) { asm volatile("cp.async.wait_group 1;" ::: "memory"); }
        else         { asm volatile("cp.async.wait_group 0;" ::: "memory"); }
        asm volatile("bar.sync %0, 64;" :: "r"(ng + 1) : "memory");

        const uint32_t wbuf = smW + (uint32_t)(c & 1) * WSLAB;
#pragma unroll
        for (int kk = 0; kk < 4; kk++) {
            const uint32_t kgA = (uint32_t)(kc * 64 + kk * 16) * 2;
            uint32_t a[2][4], bf[8][2];
#pragma unroll
            for (int mt = 0; mt < 2; mt++)
                ldm_x4(a[mt], aBase + (uint32_t)(mt * 16) * 528 + kgA);
#pragma unroll
            for (int i = 0; i < 4; i++) {
                uint32_t r[4];
                ldm_x4(r, wbuf + (uint32_t)(nbase + i * 16) * 144 + (uint32_t)(kk * 32) + bOff);
                bf[2 * i][0] = r[0]; bf[2 * i][1] = r[1];
                bf[2 * i + 1][0] = r[2]; bf[2 * i + 1][1] = r[3];
            }
#pragma unroll
            for (int mt = 0; mt < 2; mt++)
#pragma unroll
                for (int nt = 0; nt < 8; nt++)
                    mma_bf16(acc[mt][nt], a[mt], bf[nt]);
        }

        // restage this slab with chunk c+2 (group's reads of slab done)
        if (c + 2 < 12) {
            asm volatile("bar.sync %0, 64;" :: "r"(ng + 1) : "memory");
            stage(c + 2);
        }

        if (kc == 3) {          // ---- layer boundary ----
            const int L = c >> 2;
            const float* sb = sbias + L * 256;
            if (L < 2) {
                __syncthreads();   // all reads of hA (layer L) complete
#pragma unroll
                for (int mt = 0; mt < 2; mt++) {
                    const int r0 = mbase + mt * 16 + (lane >> 2);
#pragma unroll
                    for (int nt = 0; nt < 8; nt++) {
                        const int col = nbase + nt * 8 + 2 * (lane & 3);
                        const float b0 = sb[col], b1 = sb[col + 1];
                        *(uint32_t*)(smem + SB_HA + r0 * 528 + col * 2) =
                            bf2u(fmaxf(acc[mt][nt][0] + b0, 0.0f), fmaxf(acc[mt][nt][1] + b1, 0.0f));
                        *(uint32_t*)(smem + SB_HA + (r0 + 8) * 528 + col * 2) =
                            bf2u(fmaxf(acc[mt][nt][2] + b0, 0.0f), fmaxf(acc[mt][nt][3] + b1, 0.0f));
                    }
                }
#pragma unroll
                for (int mt = 0; mt < 2; mt++)
#pragma unroll
                    for (int nt = 0; nt < 8; nt++)
#pragma unroll
                        for (int i = 0; i < 4; i++) acc[mt][nt][i] = 0.0f;
                __syncthreads();   // hA(L+1) visible before reads
            } else {
                // layer 4: relu + column sums -> atomicAdd
                __syncthreads();
                float* red = (float*)(smem + SB_HA);   // reuse hA region [2][256]
#pragma unroll
                for (int nt = 0; nt < 8; nt++) {
                    const int col = nbase + nt * 8 + 2 * (lane & 3);
                    const float b0 = sb[col], b1 = sb[col + 1];
                    float s0 = 0.0f, s1 = 0.0f;
#pragma unroll
                    for (int mt = 0; mt < 2; mt++) {
                        s0 += fmaxf(acc[mt][nt][0] + b0, 0.0f) + fmaxf(acc[mt][nt][2] + b0, 0.0f);
                        s1 += fmaxf(acc[mt][nt][1] + b1, 0.0f) + fmaxf(acc[mt][nt][3] + b1, 0.0f);
                    }
#pragma unroll
                    for (int off = 4; off <= 16; off <<= 1) {
                        s0 += __shfl_xor_sync(0xffffffffu, s0, off);
                        s1 += __shfl_xor_sync(0xffffffffu, s1, off);
                    }
                    if (lane < 4) {
                        red[(wid & 1) * H + col] = s0;
                        red[(wid & 1) * H + col + 1] = s1;
                    }
                }
                __syncthreads();
                if (tid < H) atomicAdd(&g_xg[b * H + tid], red[tid] + red[H + tid]);
            }
        }
    }
}

// =====================================================================
// k_f: f-MLP + log_softmax
// =====================================================================
__global__ void k_f(const float* __restrict__ Wf1, const float* __restrict__ bf1,
                    const float* __restrict__ Wf2, const float* __restrict__ bf2,
                    const float* __restrict__ Wf3, const float* __restrict__ bf3,
                    float* __restrict__ out) {
    int b = blockIdx.x;
    int tid = threadIdx.x, lane = tid & 31, w = tid >> 5;

    __shared__ float xs[H], f1s[H], f2s[H], ls[32];

    xs[tid] = g_xg[b * H + tid];
    __syncthreads();

    for (int i = 0; i < 32; i++) {
        int n = w * 32 + i;
        float p = 0.0f;
#pragma unroll
        for (int j = 0; j < 8; j++) { int k = lane + 32 * j; p += xs[k] * Wf1[n * H + k]; }
#pragma unroll
        for (int off = 16; off > 0; off >>= 1) p += __shfl_xor_sync(0xffffffffu, p, off);
        if (lane == 0) f1s[n] = fmaxf(p + bf1[n], 0.0f);
    }
    __syncthreads();

    for (int i = 0; i < 32; i++) {
        int n = w * 32 + i;
        float p = 0.0f;
#pragma unroll
        for (int j = 0; j < 8; j++) { int k = lane + 32 * j; p += f1s[k] * Wf2[n * H + k]; }
#pragma unroll
        for (int off = 16; off > 0; off >>= 1) p += __shfl_xor_sync(0xffffffffu, p, off);
        if (lane == 0) f2s[n] = fmaxf(p + bf2[n], 0.0f);
    }
    __syncthreads();

    for (int i = 0; i < 4; i++) {
        int n = w * 4 + i;
        if (n < OUT) {
            float p = 0.0f;
#pragma unroll
            for (int j = 0; j < 8; j++) { int k = lane + 32 * j; p += f2s[k] * Wf3[n * H + k]; }
#pragma unroll
            for (int off = 16; off > 0; off >>= 1) p += __shfl_xor_sync(0xffffffffu, p, off);
            if (lane == 0) ls[n] = p + bf3[n];
        }
    }
    __syncthreads();

    if (w == 0) {
        float v = (lane < OUT) ? ls[lane] : -3.4e38f;
        float m = v;
#pragma unroll
        for (int off = 16; off > 0; off >>= 1) m = fmaxf(m, __shfl_xor_sync(0xffffffffu, m, off));
        float e = (lane < OUT) ? expf(v - m) : 0.0f;
        float s = e;
#pragma unroll
        for (int off = 16; off > 0; off >>= 1) s += __shfl_xor_sync(0xffffffffu, s, off);
        float lse = logf(s) + m;
        if (lane < OUT) out[b * OUT + lane] = v - lse;
    }
}

// =====================================================================
extern "C" void kernel_launch(void* const* d_in, const int* in_sizes, int n_in,
                              void* d_out, int out_size) {
    (void)in_sizes; (void)n_in; (void)out_size;
    const float* x   = (const float*)d_in[0];
    const float* qst = (const float*)d_in[1];
    const float* Wg1 = (const float*)d_in[2];
    const float* bg1 = (const float*)d_in[3];
    const float* Wg2 = (const float*)d_in[4];
    const float* bg2 = (const float*)d_in[5];
    const float* Wg3 = (const float*)d_in[6];
    const float* bg3 = (const float*)d_in[7];
    const float* Wg4 = (const float*)d_in[8];
    const float* bg4 = (const float*)d_in[9];
    const float* Wf1 = (const float*)d_in[10];
    const float* bf1 = (const float*)d_in[11];
    const float* Wf2 = (const float*)d_in[12];
    const float* bf2 = (const float*)d_in[13];
    const float* Wf3 = (const float*)d_in[14];
    const float* bf3 = (const float*)d_in[15];

    cudaFuncSetAttribute(k_g, cudaFuncAttributeMaxDynamicSharedMemorySize, SB_TOTAL);

    k_prep<<<512, 256>>>(x, qst, Wg1, bg1, Wg2, Wg3, Wg4);
    k_g<<<dim3(S2, MB), NTHREADS, SB_TOTAL>>>(bg2, bg3, bg4);
    k_f<<<MB, 256>>>(Wf1, bf1, Wf2, bf2, Wf3, bf3, (float*)d_out);
}

// round 12
// speedup vs baseline: 18.6144x; 1.0299x over previous
#include <cuda_runtime.h>
#include <cuda_bf16.h>
#include <cstdint>
#include <math.h>

#define MB   64
#define C    24
#define S2   64
#define QS   128
#define H    256
#define OUT  28

#define NTHREADS 256

// k_g smem layout (bytes)
#define SB_BIAS  0                       // 3*256 floats = 3072
#define SB_HA    3072                    // 128 * 528    = 67584
#define SB_WS    70656                   // 2 * 36864    = 73728
#define SB_TOTAL 144384
#define WSLAB    36864                   // one K64 chunk: 256 rows * 144 B

// ---------------- scratch ----------------
__device__ float g_u[MB * S2 * H];
__device__ float g_v[MB * S2 * H];
__device__ float g_w[MB * H];
__device__ float g_xg[MB * H];
__device__ __align__(16) __nv_bfloat16 g_Wb[3 * H * H];

// ---------------- helpers ----------------
__device__ __forceinline__ uint32_t smem_u32(const void* p) {
    uint32_t a;
    asm("{ .reg .u64 t; cvta.to.shared.u64 t, %1; cvt.u32.u64 %0, t; }" : "=r"(a) : "l"(p));
    return a;
}
__device__ __forceinline__ void cp16(uint32_t dst, const void* src) {
    asm volatile("cp.async.ca.shared.global [%0], [%1], 16;" :: "r"(dst), "l"(src) : "memory");
}
__device__ __forceinline__ void cp_commit() {
    asm volatile("cp.async.commit_group;" ::: "memory");
}
__device__ __forceinline__ void ldm_x4(uint32_t* r, uint32_t addr) {
    asm volatile("ldmatrix.sync.aligned.m8n8.x4.shared.b16 {%0,%1,%2,%3}, [%4];"
                 : "=r"(r[0]), "=r"(r[1]), "=r"(r[2]), "=r"(r[3]) : "r"(addr));
}
__device__ __forceinline__ void mma_bf16(float* d, const uint32_t* a, const uint32_t* b) {
    asm volatile(
        "mma.sync.aligned.m16n8k16.row.col.f32.bf16.bf16.f32 "
        "{%0,%1,%2,%3}, {%4,%5,%6,%7}, {%8,%9}, {%0,%1,%2,%3};"
        : "+f"(d[0]), "+f"(d[1]), "+f"(d[2]), "+f"(d[3])
        : "r"(a[0]), "r"(a[1]), "r"(a[2]), "r"(a[3]), "r"(b[0]), "r"(b[1]));
}
__device__ __forceinline__ uint32_t bf2u(float a, float b) {
    __nv_bfloat162 h = __floats2bfloat162_rn(a, b);
    return *(uint32_t*)&h;
}

// =====================================================================
// k_prep: fused  [0,192): W->bf16   [192,256): qw   [256,512): uv
// =====================================================================
__global__ void k_prep(const float* __restrict__ x, const float* __restrict__ qst,
                       const float* __restrict__ Wg1, const float* __restrict__ bg1,
                       const float* __restrict__ W2, const float* __restrict__ W3,
                       const float* __restrict__ W4) {
    const int bid = blockIdx.x, tid = threadIdx.x;

    if (bid < 192) {
        int l = bid >> 6, blk = bid & 63;
        const float* W = (l == 0) ? W2 : (l == 1) ? W3 : W4;
        int i = (blk * 256 + tid) * 4;
        float4 v = *(const float4*)(W + i);
        uint2 o;
        o.x = bf2u(v.x, v.y);
        o.y = bf2u(v.z, v.w);
        *(uint2*)(g_Wb + l * H * H + i) = o;
        return;
    }
    if (bid < 256) {
        int b = bid - 192;
        int lane = tid & 31, w = tid >> 5;
        __shared__ float qs[QS];
        if (tid < QS) qs[tid] = qst[b * QS + tid];
        __syncthreads();
        for (int i = 0; i < 32; i++) {
            int n = w * 32 + i;
            const float* wr = Wg1 + n * 180 + 52;
            float p = 0.0f;
#pragma unroll
            for (int j = 0; j < 4; j++) p += qs[lane + 32 * j] * wr[lane + 32 * j];
#pragma unroll
            for (int off = 16; off > 0; off >>= 1) p += __shfl_xor_sync(0xffffffffu, p, off);
            if (lane == 0) g_w[b * H + n] = p + bg1[n];
        }
        return;
    }
    {
        int idx = bid - 256;
        int b = idx >> 2, seg = idx & 3;
        __shared__ float xf[16][26];
        for (int i = tid; i < 16 * C; i += 256) {
            int c = i / 16, sl = i % 16;
            xf[sl][c] = x[(b * C + c) * S2 + seg * 16 + sl];
        }
        if (tid < 16) {
            int s = seg * 16 + tid;
            xf[tid][24] = ((s >> 3) - 4) * 0.25f;
            xf[tid][25] = ((s & 7) - 4) * 0.25f;
        }
        if (seg == 0) g_xg[b * H + tid] = 0.0f;
        __syncthreads();

        const int n = tid;
        const float* wr = Wg1 + n * 180;
        float Wi[26], Wj[26];
#pragma unroll
        for (int c = 0; c < 26; c++) { Wi[c] = wr[c]; Wj[c] = wr[26 + c]; }
        for (int sl = 0; sl < 16; sl++) {
            float su = 0.0f, sv = 0.0f;
#pragma unroll
            for (int c = 0; c < 26; c++) {
                float xv = xf[sl][c];
                su += xv * Wi[c];
                sv += xv * Wj[c];
            }
            int s = seg * 16 + sl;
            g_u[(b * S2 + s) * H + n] = su;
            g_v[(b * S2 + s) * H + n] = sv;
        }
    }
}

// =====================================================================
// k_g: bf16 mma.sync g-MLP.  CTA = (2 p-rows, batch): M=128,N=256,K=256.
//   8 warps 2(m:64) x 4(n:64), warp tile 64x64 (acc 128 regs).
//   Double-buffered K64 weight slabs, per-n-group staging (2 warps/group).
// =====================================================================
__global__ void __launch_bounds__(NTHREADS, 1)
k_g(const float* __restrict__ bg2, const float* __restrict__ bg3,
    const float* __restrict__ bg4) {
    extern __shared__ char smem[];
    float* sbias = (float*)(smem + SB_BIAS);

    const int b = blockIdx.y, tile = blockIdx.x;   // tile: 2 p-rows
    const int tid = threadIdx.x, wid = tid >> 5, lane = tid & 31;
    const int mbase = (wid & 1) * 64;              // warp m-offset (64-row tile)
    const int ng = wid >> 1;                       // n-group 0..3 (2 warps)
    const int nbase = ng * 64;
    const int wtid = tid & 63;

    const uint32_t smA = smem_u32(smem + SB_HA);
    const uint32_t smW = smem_u32(smem + SB_WS);

    const uint32_t aBase = smA + (uint32_t)(mbase + (lane & 15)) * 528 + (uint32_t)(lane >> 4) * 16;
    const uint32_t bOff  = (uint32_t)(((lane >> 4) * 8 + (lane & 7)) * 144 + ((lane >> 3) & 1) * 16);

    if (tid < 256) {
        sbias[tid]       = bg2[tid];
        sbias[256 + tid] = bg3[tid];
        sbias[512 + tid] = bg4[tid];
    }

    // stage chunk c into slab c&1 (per n-group rows [nbase, nbase+64))
    auto stage = [&](int c) {
        const int L = c >> 2, kc = c & 3;
        const __nv_bfloat16* Wb = g_Wb + L * H * H + kc * 64;
        const uint32_t dst = smW + (uint32_t)(c & 1) * WSLAB;
#pragma unroll
        for (int it = 0; it < 8; it++) {
            int idx = wtid + it * 64;              // 0..511
            int nl = idx >> 3, k8 = idx & 7;
            int n = nbase + nl;
            cp16(dst + (uint32_t)(n * 144 + k8 * 16), Wb + n * H + k8 * 8);
        }
        cp_commit();
    };

    stage(0);
    stage(1);

    // ---- build h1 = relu(u[q] + v[p] + w[n]) in bf16 (128 rows) ----
    const float* ub = g_u + b * S2 * H;
    const float* vb = g_v + b * S2 * H;
    const float* wb_ = g_w + b * H;
#pragma unroll
    for (int it = 0; it < 16; it++) {
        int i = tid + it * NTHREADS;               // 0..4095
        int r = i >> 5, kb = (i & 31) * 8;
        int q = r & 63, p = tile * 2 + (r >> 6);
        float4 u0 = *(const float4*)(ub + q * H + kb);
        float4 u1 = *(const float4*)(ub + q * H + kb + 4);
        float4 v0 = *(const float4*)(vb + p * H + kb);
        float4 v1 = *(const float4*)(vb + p * H + kb + 4);
        float4 w0 = *(const float4*)(wb_ + kb);
        float4 w1 = *(const float4*)(wb_ + kb + 4);
        uint4 o;
        o.x = bf2u(fmaxf(u0.x + v0.x + w0.x, 0.0f), fmaxf(u0.y + v0.y + w0.y, 0.0f));
        o.y = bf2u(fmaxf(u0.z + v0.z + w0.z, 0.0f), fmaxf(u0.w + v0.w + w0.w, 0.0f));
        o.z = bf2u(fmaxf(u1.x + v1.x + w1.x, 0.0f), fmaxf(u1.y + v1.y + w1.y, 0.0f));
        o.w = bf2u(fmaxf(u1.z + v1.z + w1.z, 0.0f), fmaxf(u1.w + v1.w + w1.w, 0.0f));
        *(uint4*)(smem + SB_HA + r * 528 + kb * 2) = o;
    }
    __syncthreads();

    float acc[4][8][4];
#pragma unroll
    for (int mt = 0; mt < 4; mt++)
#pragma unroll
        for (int nt = 0; nt < 8; nt++)
#pragma unroll
            for (int i = 0; i < 4; i++) acc[mt][nt][i] = 0.0f;

    for (int c = 0; c < 12; c++) {
        const int kc = c & 3;

        if (c <= 10) { asm volatile("cp.async.wait_group 1;" ::: "memory"); }
        else         { asm volatile("cp.async.wait_group 0;" ::: "memory"); }
        asm volatile("bar.sync %0, 64;" :: "r"(ng + 1) : "memory");

        const uint32_t wbuf = smW + (uint32_t)(c & 1) * WSLAB;
#pragma unroll
        for (int kk = 0; kk < 4; kk++) {
            const uint32_t kgA = (uint32_t)(kc * 64 + kk * 16) * 2;
            uint32_t a[4][4];
#pragma unroll
            for (int mt = 0; mt < 4; mt++)
                ldm_x4(a[mt], aBase + (uint32_t)(mt * 16) * 528 + kgA);
#pragma unroll
            for (int i = 0; i < 4; i++) {
                uint32_t r[4];
                ldm_x4(r, wbuf + (uint32_t)(nbase + i * 16) * 144 + (uint32_t)(kk * 32) + bOff);
#pragma unroll
                for (int mt = 0; mt < 4; mt++) {
                    mma_bf16(acc[mt][2 * i],     a[mt], r);
                    mma_bf16(acc[mt][2 * i + 1], a[mt], r + 2);
                }
            }
        }

        if (c + 2 < 12) {
            asm volatile("bar.sync %0, 64;" :: "r"(ng + 1) : "memory");
            stage(c + 2);
        }

        if (kc == 3) {          // ---- layer boundary ----
            const int L = c >> 2;
            const float* sb = sbias + L * 256;
            if (L < 2) {
                __syncthreads();   // all reads of hA (layer L) complete
#pragma unroll
                for (int mt = 0; mt < 4; mt++) {
                    const int r0 = mbase + mt * 16 + (lane >> 2);
#pragma unroll
                    for (int nt = 0; nt < 8; nt++) {
                        const int col = nbase + nt * 8 + 2 * (lane & 3);
                        const float b0 = sb[col], b1 = sb[col + 1];
                        *(uint32_t*)(smem + SB_HA + r0 * 528 + col * 2) =
                            bf2u(fmaxf(acc[mt][nt][0] + b0, 0.0f), fmaxf(acc[mt][nt][1] + b1, 0.0f));
                        *(uint32_t*)(smem + SB_HA + (r0 + 8) * 528 + col * 2) =
                            bf2u(fmaxf(acc[mt][nt][2] + b0, 0.0f), fmaxf(acc[mt][nt][3] + b1, 0.0f));
                    }
                }
#pragma unroll
                for (int mt = 0; mt < 4; mt++)
#pragma unroll
                    for (int nt = 0; nt < 8; nt++)
#pragma unroll
                        for (int i = 0; i < 4; i++) acc[mt][nt][i] = 0.0f;
                __syncthreads();   // hA(L+1) visible before reads
            } else {
                // layer 4: relu + column sums -> atomicAdd
                __syncthreads();
                float* red = (float*)(smem + SB_HA);   // [2][256]
#pragma unroll
                for (int nt = 0; nt < 8; nt++) {
                    const int col = nbase + nt * 8 + 2 * (lane & 3);
                    const float b0 = sb[col], b1 = sb[col + 1];
                    float s0 = 0.0f, s1 = 0.0f;
#pragma unroll
                    for (int mt = 0; mt < 4; mt++) {
                        s0 += fmaxf(acc[mt][nt][0] + b0, 0.0f) + fmaxf(acc[mt][nt][2] + b0, 0.0f);
                        s1 += fmaxf(acc[mt][nt][1] + b1, 0.0f) + fmaxf(acc[mt][nt][3] + b1, 0.0f);
                    }
#pragma unroll
                    for (int off = 4; off <= 16; off <<= 1) {
                        s0 += __shfl_xor_sync(0xffffffffu, s0, off);
                        s1 += __shfl_xor_sync(0xffffffffu, s1, off);
                    }
                    if (lane < 4) {
                        red[(wid & 1) * H + col] = s0;
                        red[(wid & 1) * H + col + 1] = s1;
                    }
                }
                __syncthreads();
                if (tid < H) atomicAdd(&g_xg[b * H + tid], red[tid] + red[H + tid]);
            }
        }
    }
}

// =====================================================================
// k_f: f-MLP + log_softmax
// =====================================================================
__global__ void k_f(const float* __restrict__ Wf1, const float* __restrict__ bf1,
                    const float* __restrict__ Wf2, const float* __restrict__ bf2,
                    const float* __restrict__ Wf3, const float* __restrict__ bf3,
                    float* __restrict__ out) {
    int b = blockIdx.x;
    int tid = threadIdx.x, lane = tid & 31, w = tid >> 5;

    __shared__ float xs[H], f1s[H], f2s[H], ls[32];

    xs[tid] = g_xg[b * H + tid];
    __syncthreads();

    for (int i = 0; i < 32; i++) {
        int n = w * 32 + i;
        float p = 0.0f;
#pragma unroll
        for (int j = 0; j < 8; j++) { int k = lane + 32 * j; p += xs[k] * Wf1[n * H + k]; }
#pragma unroll
        for (int off = 16; off > 0; off >>= 1) p += __shfl_xor_sync(0xffffffffu, p, off);
        if (lane == 0) f1s[n] = fmaxf(p + bf1[n], 0.0f);
    }
    __syncthreads();

    for (int i = 0; i < 32; i++) {
        int n = w * 32 + i;
        float p = 0.0f;
#pragma unroll
        for (int j = 0; j < 8; j++) { int k = lane + 32 * j; p += f1s[k] * Wf2[n * H + k]; }
#pragma unroll
        for (int off = 16; off > 0; off >>= 1) p += __shfl_xor_sync(0xffffffffu, p, off);
        if (lane == 0) f2s[n] = fmaxf(p + bf2[n], 0.0f);
    }
    __syncthreads();

    for (int i = 0; i < 4; i++) {
        int n = w * 4 + i;
        if (n < OUT) {
            float p = 0.0f;
#pragma unroll
            for (int j = 0; j < 8; j++) { int k = lane + 32 * j; p += f2s[k] * Wf3[n * H + k]; }
#pragma unroll
            for (int off = 16; off > 0; off >>= 1) p += __shfl_xor_sync(0xffffffffu, p, off);
            if (lane == 0) ls[n] = p + bf3[n];
        }
    }
    __syncthreads();

    if (w == 0) {
        float v = (lane < OUT) ? ls[lane] : -3.4e38f;
        float m = v;
#pragma unroll
        for (int off = 16; off > 0; off >>= 1) m = fmaxf(m, __shfl_xor_sync(0xffffffffu, m, off));
        float e = (lane < OUT) ? expf(v - m) : 0.0f;
        float s = e;
#pragma unroll
        for (int off = 16; off > 0; off >>= 1) s += __shfl_xor_sync(0xffffffffu, s, off);
        float lse = logf(s) + m;
        if (lane < OUT) out[b * OUT + lane] = v - lse;
    }
}

// =====================================================================
extern "C" void kernel_launch(void* const* d_in, const int* in_sizes, int n_in,
                              void* d_out, int out_size) {
    (void)in_sizes; (void)n_in; (void)out_size;
    const float* x   = (const float*)d_in[0];
    const float* qst = (const float*)d_in[1];
    const float* Wg1 = (const float*)d_in[2];
    const float* bg1 = (const float*)d_in[3];
    const float* Wg2 = (const float*)d_in[4];
    const float* bg2 = (const float*)d_in[5];
    const float* Wg3 = (const float*)d_in[6];
    const float* bg3 = (const float*)d_in[7];
    const float* Wg4 = (const float*)d_in[8];
    const float* bg4 = (const float*)d_in[9];
    const float* Wf1 = (const float*)d_in[10];
    const float* bf1 = (const float*)d_in[11];
    const float* Wf2 = (const float*)d_in[12];
    const float* bf2 = (const float*)d_in[13];
    const float* Wf3 = (const float*)d_in[14];
    const float* bf3 = (const float*)d_in[15];

    cudaFuncSetAttribute(k_g, cudaFuncAttributeMaxDynamicSharedMemorySize, SB_TOTAL);

    k_prep<<<512, 256>>>(x, qst, Wg1, bg1, Wg2, Wg3, Wg4);
    k_g<<<dim3(S2 * S2 / 128, MB), NTHREADS, SB_TOTAL>>>(bg2, bg3, bg4);
    k_f<<<MB, 256>>>(Wf1, bf1, Wf2, bf2, Wf3, bf3, (float*)d_out);
}